// round 1
// baseline (speedup 1.0000x reference)
#include <cuda_runtime.h>
#include <math.h>

// Problem constants (fixed by the reference)
#define Bn   4
#define Sn   2048
#define Dn   1024
#define Hn   16
#define HDn  64
#define HHD  (Hn*HDn)      // 1024
#define QKVROW (3*HHD)     // 3072
#define Mrows (Bn*Sn)      // 8192

// Scratch (allocation-free: device globals)
__device__ float g_qkv[(size_t)Bn * Sn * 3 * Hn * HDn];   // [8192, 3072]
__device__ float g_att[(size_t)Bn * Sn * Hn * HDn];       // [8192, 1024]

// ---------------------------------------------------------------------------
// SGEMM: C[M,N] = A[M,K] @ B[K,N] + bias[N]
// Tile 128x128, BK=8, 256 threads, 8x8 per-thread (z-split 64+64 layout).
// Assumes M%128==0, N%128==0, K%8==0 (true for all three calls).
// ---------------------------------------------------------------------------
__global__ __launch_bounds__(256) void sgemm_bias_kernel(
    const float* __restrict__ A, const float* __restrict__ Bm,
    const float* __restrict__ bias, float* __restrict__ C,
    int M, int N, int K)
{
    __shared__ float As[8][132];   // A tile stored transposed [k][m], padded
    __shared__ float Bs[8][128];   // B tile [k][n]

    const int tid = threadIdx.x;
    const int tx  = tid & 15;
    const int ty  = tid >> 4;
    const int bm0 = blockIdx.y * 128;
    const int bn0 = blockIdx.x * 128;

    // global load mapping
    const int arow = tid >> 1;          // 0..127
    const int acol = (tid & 1) * 4;     // 0 or 4
    const int brow = tid >> 5;          // 0..7
    const int bcol = (tid & 31) * 4;    // 0..124

    const float* Aptr = A + (size_t)(bm0 + arow) * K + acol;
    const float* Bptr = Bm + (size_t)brow * N + bn0 + bcol;

    float4 av = *(const float4*)Aptr;
    float4 bv = *(const float4*)Bptr;

    float acc[8][8];
#pragma unroll
    for (int i = 0; i < 8; i++)
#pragma unroll
        for (int j = 0; j < 8; j++) acc[i][j] = 0.f;

    for (int k0 = 0; k0 < K; k0 += 8) {
        __syncthreads();
        As[acol + 0][arow] = av.x;
        As[acol + 1][arow] = av.y;
        As[acol + 2][arow] = av.z;
        As[acol + 3][arow] = av.w;
        *(float4*)&Bs[brow][bcol] = bv;
        __syncthreads();

        if (k0 + 8 < K) {   // prefetch next tile into registers
            av = *(const float4*)(Aptr + k0 + 8);
            bv = *(const float4*)(Bptr + (size_t)(k0 + 8) * N);
        }

#pragma unroll
        for (int kk = 0; kk < 8; kk++) {
            float4 a0 = *(const float4*)&As[kk][ty * 4];
            float4 a1 = *(const float4*)&As[kk][64 + ty * 4];
            float4 b0 = *(const float4*)&Bs[kk][tx * 4];
            float4 b1 = *(const float4*)&Bs[kk][64 + tx * 4];
            float a[8] = {a0.x, a0.y, a0.z, a0.w, a1.x, a1.y, a1.z, a1.w};
            float b[8] = {b0.x, b0.y, b0.z, b0.w, b1.x, b1.y, b1.z, b1.w};
#pragma unroll
            for (int i = 0; i < 8; i++)
#pragma unroll
                for (int j = 0; j < 8; j++)
                    acc[i][j] = fmaf(a[i], b[j], acc[i][j]);
        }
    }

    // epilogue: bias + store (all aligned, exact bounds)
#pragma unroll
    for (int cj = 0; cj < 2; cj++) {
        int col = bn0 + cj * 64 + tx * 4;
        float4 bb = *(const float4*)&bias[col];
#pragma unroll
        for (int ri = 0; ri < 2; ri++) {
#pragma unroll
            for (int i = 0; i < 4; i++) {
                int row = bm0 + ri * 64 + ty * 4 + i;
                float4 o;
                o.x = acc[ri * 4 + i][cj * 4 + 0] + bb.x;
                o.y = acc[ri * 4 + i][cj * 4 + 1] + bb.y;
                o.z = acc[ri * 4 + i][cj * 4 + 2] + bb.z;
                o.w = acc[ri * 4 + i][cj * 4 + 3] + bb.w;
                *(float4*)&C[(size_t)row * N + col] = o;
            }
        }
    }
}

// ---------------------------------------------------------------------------
// Flash attention (fp32, causal). One CTA per (b, h, 64-row q tile).
// 256 threads as 16x16; each thread owns a 4x4 tile of S and of O.
// qkv layout: [B*S, 3*H*HD] (GEMM1 output), Q at col h*HD, K at +HHD, V +2*HHD.
// ---------------------------------------------------------------------------
#define LDP 68   // smem row pitch (floats): 68*4B = 272B, 16B-aligned, low-conflict

__global__ __launch_bounds__(256) void attn_kernel(const float* __restrict__ qkv,
                                                   float* __restrict__ outp)
{
    extern __shared__ float sm[];
    float* Qs = sm;                 // [64][LDP]  (m-major)
    float* Ks = sm + 64 * LDP;      // [64][LDP]  (d-major: Ks[d][n])
    float* Vs = sm + 2 * 64 * LDP;  // [64][LDP]  (n-major: Vs[n][d])
    float* Ps = sm + 3 * 64 * LDP;  // [64][LDP]

    const int tid = threadIdx.x;
    const int tx  = tid & 15;
    const int ty  = tid >> 4;
    const int qt  = blockIdx.x;
    const int h   = blockIdx.y;
    const int b   = blockIdx.z;
    const int q0  = qt * 64;

    // ---- load Q tile (64x64) ----
#pragma unroll
    for (int r = 0; r < 4; r++) {
        int e  = tid + r * 256;
        int m  = e >> 4;
        int dg = (e & 15) << 2;
        const float* p = qkv + (size_t)(b * Sn + q0 + m) * QKVROW + h * HDn + dg;
        *(float4*)&Qs[m * LDP + dg] = *(const float4*)p;
    }

    float o[4][4];
    float mr[4], lr[4];
#pragma unroll
    for (int i = 0; i < 4; i++) {
        mr[i] = -INFINITY; lr[i] = 0.f;
#pragma unroll
        for (int j = 0; j < 4; j++) o[i][j] = 0.f;
    }

    for (int kt = 0; kt <= qt; kt++) {
        __syncthreads();   // prior PV reads of Ks/Vs/Ps complete
        // ---- load K (transposed -> d-major) and V tiles ----
#pragma unroll
        for (int r = 0; r < 4; r++) {
            int e  = tid + r * 256;
            int n  = e >> 4;
            int dg = (e & 15) << 2;
            const float* p = qkv + (size_t)(b * Sn + kt * 64 + n) * QKVROW + HHD + h * HDn + dg;
            float4 kv = *(const float4*)p;
            Ks[(dg + 0) * LDP + n] = kv.x;
            Ks[(dg + 1) * LDP + n] = kv.y;
            Ks[(dg + 2) * LDP + n] = kv.z;
            Ks[(dg + 3) * LDP + n] = kv.w;
            float4 vv = *(const float4*)(p + HHD);
            *(float4*)&Vs[n * LDP + dg] = vv;
        }
        __syncthreads();

        // ---- S = Q @ K^T (4x4 per thread) ----
        float s[4][4];
#pragma unroll
        for (int i = 0; i < 4; i++)
#pragma unroll
            for (int j = 0; j < 4; j++) s[i][j] = 0.f;

#pragma unroll 4
        for (int d = 0; d < 64; d++) {
            float4 kf = *(const float4*)&Ks[d * LDP + tx * 4];
#pragma unroll
            for (int i = 0; i < 4; i++) {
                float qv = Qs[(ty * 4 + i) * LDP + d];
                s[i][0] = fmaf(qv, kf.x, s[i][0]);
                s[i][1] = fmaf(qv, kf.y, s[i][1]);
                s[i][2] = fmaf(qv, kf.z, s[i][2]);
                s[i][3] = fmaf(qv, kf.w, s[i][3]);
            }
        }

        // ---- scale + causal mask ----
        const float scale = 0.125f;   // rsqrt(64)
        if (kt == qt) {
#pragma unroll
            for (int i = 0; i < 4; i++) {
                int qg = ty * 4 + i;
#pragma unroll
                for (int j = 0; j < 4; j++) {
                    int kg = tx * 4 + j;
                    s[i][j] = (kg <= qg) ? s[i][j] * scale : -1e30f;
                }
            }
        } else {
#pragma unroll
            for (int i = 0; i < 4; i++)
#pragma unroll
                for (int j = 0; j < 4; j++) s[i][j] *= scale;
        }

        // ---- online softmax (row groups = 16 lanes sharing ty) ----
#pragma unroll
        for (int i = 0; i < 4; i++) {
            float tm = fmaxf(fmaxf(s[i][0], s[i][1]), fmaxf(s[i][2], s[i][3]));
#pragma unroll
            for (int off = 8; off > 0; off >>= 1)
                tm = fmaxf(tm, __shfl_xor_sync(0xffffffffu, tm, off));
            float mnew = fmaxf(mr[i], tm);
            float c = __expf(mr[i] - mnew);   // first iter: exp(-inf)=0
            mr[i] = mnew;
            float rs = 0.f;
#pragma unroll
            for (int j = 0; j < 4; j++) {
                s[i][j] = __expf(s[i][j] - mnew);
                rs += s[i][j];
            }
#pragma unroll
            for (int off = 8; off > 0; off >>= 1)
                rs += __shfl_xor_sync(0xffffffffu, rs, off);
            lr[i] = lr[i] * c + rs;
#pragma unroll
            for (int j = 0; j < 4; j++) o[i][j] *= c;
        }

        // ---- stage P to smem ----
#pragma unroll
        for (int i = 0; i < 4; i++)
            *(float4*)&Ps[(ty * 4 + i) * LDP + tx * 4] =
                make_float4(s[i][0], s[i][1], s[i][2], s[i][3]);
        __syncthreads();

        // ---- O += P @ V ----
#pragma unroll 4
        for (int n = 0; n < 64; n++) {
            float4 vf = *(const float4*)&Vs[n * LDP + tx * 4];
#pragma unroll
            for (int i = 0; i < 4; i++) {
                float pv = Ps[(ty * 4 + i) * LDP + n];
                o[i][0] = fmaf(pv, vf.x, o[i][0]);
                o[i][1] = fmaf(pv, vf.y, o[i][1]);
                o[i][2] = fmaf(pv, vf.z, o[i][2]);
                o[i][3] = fmaf(pv, vf.w, o[i][3]);
            }
        }
    }

    // ---- normalize + store ----
#pragma unroll
    for (int i = 0; i < 4; i++) {
        float inv = 1.f / lr[i];
        float* p = outp + (size_t)(b * Sn + q0 + ty * 4 + i) * HHD + h * HDn + tx * 4;
        *(float4*)p = make_float4(o[i][0] * inv, o[i][1] * inv,
                                  o[i][2] * inv, o[i][3] * inv);
    }
}

// ---------------------------------------------------------------------------
extern "C" void kernel_launch(void* const* d_in, const int* in_sizes, int n_in,
                              void* d_out, int out_size)
{
    const float* x      = (const float*)d_in[0];
    const float* w_qkv  = (const float*)d_in[1];
    const float* b_qkv  = (const float*)d_in[2];
    const float* w_proj = (const float*)d_in[3];
    const float* b_proj = (const float*)d_in[4];
    float* out = (float*)d_out;

    float* qkv; float* att;
    cudaGetSymbolAddress((void**)&qkv, g_qkv);
    cudaGetSymbolAddress((void**)&att, g_att);

    const int smem = 4 * 64 * LDP * (int)sizeof(float);   // 69,632 B
    cudaFuncSetAttribute(attn_kernel,
                         cudaFuncAttributeMaxDynamicSharedMemorySize, smem);

    // 1) QKV GEMM: [8192,1024] @ [1024,3072] + bias
    sgemm_bias_kernel<<<dim3(QKVROW / 128, Mrows / 128), 256>>>(
        x, w_qkv, b_qkv, qkv, Mrows, QKVROW, Dn);

    // 2) causal flash attention
    attn_kernel<<<dim3(Sn / 64, Hn, Bn), 256, smem>>>(qkv, att);

    // 3) proj GEMM: [8192,1024] @ [1024,1024] + bias
    sgemm_bias_kernel<<<dim3(Dn / 128, Mrows / 128), 256>>>(
        att, w_proj, b_proj, out, Mrows, Dn, HHD);
}

// round 3
// speedup vs baseline: 1.4010x; 1.4010x over previous
#include <cuda_runtime.h>
#include <cuda_bf16.h>
#include <math.h>
#include <stdint.h>

// Problem constants
#define Bn   4
#define Sn   2048
#define Dn   1024
#define Hn   16
#define HDn  64
#define HHD  (Hn*HDn)      // 1024
#define QKVROW (3*HHD)     // 3072
#define Mrows (Bn*Sn)      // 8192

// ---------------- scratch (allocation-free device globals) ----------------
__device__ __align__(128) float g_qkv[(size_t)Mrows * QKVROW];            // fp32 QKV
__device__ __align__(128) __nv_bfloat16 g_xhi[(size_t)Mrows * Dn];
__device__ __align__(128) __nv_bfloat16 g_xlo[(size_t)Mrows * Dn];
__device__ __align__(128) __nv_bfloat16 g_wqkv_hi[(size_t)Dn * QKVROW];   // [K][N]
__device__ __align__(128) __nv_bfloat16 g_wqkv_lo[(size_t)Dn * QKVROW];
__device__ __align__(128) __nv_bfloat16 g_wproj_hi[(size_t)HHD * Dn];     // [K][N]
__device__ __align__(128) __nv_bfloat16 g_wproj_lo[(size_t)HHD * Dn];
__device__ __align__(128) __nv_bfloat16 g_att_hi[(size_t)Mrows * HHD];
__device__ __align__(128) __nv_bfloat16 g_att_lo[(size_t)Mrows * HHD];

// ---------------- PTX helpers ----------------
__device__ __forceinline__ uint32_t smem_u32(const void* p) {
    uint32_t a;
    asm("{ .reg .u64 t; cvta.to.shared.u64 t, %1; cvt.u32.u64 %0, t; }" : "=r"(a) : "l"(p));
    return a;
}
#define CP16(s, g) asm volatile("cp.async.cg.shared.global [%0], [%1], 16;" :: "r"(s), "l"(g))
#define CP_COMMIT() asm volatile("cp.async.commit_group;" ::: "memory")
#define CP_WAIT1()  asm volatile("cp.async.wait_group 1;" ::: "memory")
#define CP_WAIT0()  asm volatile("cp.async.wait_group 0;" ::: "memory")

__device__ __forceinline__ void ldsm_x4(uint32_t (&r)[4], uint32_t addr) {
    asm volatile("ldmatrix.sync.aligned.m8n8.x4.shared.b16 {%0,%1,%2,%3}, [%4];"
                 : "=r"(r[0]), "=r"(r[1]), "=r"(r[2]), "=r"(r[3]) : "r"(addr));
}
__device__ __forceinline__ void ldsm_x4_t(uint32_t (&r)[4], uint32_t addr) {
    asm volatile("ldmatrix.sync.aligned.m8n8.x4.trans.shared.b16 {%0,%1,%2,%3}, [%4];"
                 : "=r"(r[0]), "=r"(r[1]), "=r"(r[2]), "=r"(r[3]) : "r"(addr));
}
__device__ __forceinline__ void mma_bf16(float (&c)[4], const uint32_t (&a)[4],
                                         uint32_t b0, uint32_t b1) {
    asm volatile(
        "mma.sync.aligned.m16n8k16.row.col.f32.bf16.bf16.f32 "
        "{%0,%1,%2,%3}, {%4,%5,%6,%7}, {%8,%9}, {%0,%1,%2,%3};"
        : "+f"(c[0]), "+f"(c[1]), "+f"(c[2]), "+f"(c[3])
        : "r"(a[0]), "r"(a[1]), "r"(a[2]), "r"(a[3]), "r"(b0), "r"(b1));
}

// ---------------- bf16 split prep ----------------
__global__ __launch_bounds__(256) void split_bf16_kernel(
    const float* __restrict__ in, __nv_bfloat16* __restrict__ hi,
    __nv_bfloat16* __restrict__ lo)
{
    int i = blockIdx.x * 256 + threadIdx.x;   // float4 index
    float4 v = ((const float4*)in)[i];
    __nv_bfloat16 h0 = __float2bfloat16(v.x);
    __nv_bfloat16 h1 = __float2bfloat16(v.y);
    __nv_bfloat16 h2 = __float2bfloat16(v.z);
    __nv_bfloat16 h3 = __float2bfloat16(v.w);
    __nv_bfloat162 ph0 = {h0, h1}, ph1 = {h2, h3};
    __nv_bfloat162 pl0 = {__float2bfloat16(v.x - __bfloat162float(h0)),
                          __float2bfloat16(v.y - __bfloat162float(h1))};
    __nv_bfloat162 pl1 = {__float2bfloat16(v.z - __bfloat162float(h2)),
                          __float2bfloat16(v.w - __bfloat162float(h3))};
    ((__nv_bfloat162*)hi)[i * 2 + 0] = ph0;
    ((__nv_bfloat162*)hi)[i * 2 + 1] = ph1;
    ((__nv_bfloat162*)lo)[i * 2 + 0] = pl0;
    ((__nv_bfloat162*)lo)[i * 2 + 1] = pl1;
}

// ---------------- bf16 split-3MMA tensor-core GEMM ----------------
// C[M,N] = A[M,K] @ B[K,N] + bias; A,B given as bf16 hi/lo pairs.
// CTA tile 128x128, BK=32, 8 warps (2x4), warp tile 64x32, double-buffered cp.async.
#define BM 128
#define BN 128
#define BKc 32
#define LDA 40     // padded A row (bf16 elems): 80B, 16B-aligned, conflict-free ldmatrix
#define LDB 136    // padded B row: 272B
#define A_BYTES (BM * LDA * 2)          // 10240
#define B_BYTES (BKc * LDB * 2)         // 8704
#define STAGE   (2 * A_BYTES + 2 * B_BYTES)  // 37888
#define SMEM_G  (2 * STAGE)             // 75776

__global__ __launch_bounds__(256) void gemm_bf16x3_kernel(
    const __nv_bfloat16* __restrict__ Ahi, const __nv_bfloat16* __restrict__ Alo,
    const __nv_bfloat16* __restrict__ Bhi, const __nv_bfloat16* __restrict__ Blo,
    const float* __restrict__ bias, float* __restrict__ C,
    int M, int N, int K)
{
    extern __shared__ char smg[];
    const uint32_t sb = smem_u32(smg);
    const int tid  = threadIdx.x;
    const int wid  = tid >> 5;
    const int lane = tid & 31;
    const int wm   = wid & 1;          // 2 m-slots of 64
    const int wn   = wid >> 1;         // 4 n-slots of 32
    const int n0   = blockIdx.x * BN;
    const int m0   = blockIdx.y * BM;
    const int NC   = K / BKc;

    // global load geometry
    const int a_row = tid >> 2, a_c = tid & 3;      // +r*64 rows
    const int b_row = tid >> 4, b_c = tid & 15;     // +r*16 rows

    auto issue = [&](int c) {
        const uint32_t sa = sb + (uint32_t)(c & 1) * STAGE;
        const int k0 = c * BKc;
#pragma unroll
        for (int r = 0; r < 2; r++) {
            int row = a_row + r * 64;
            uint32_t d = sa + (uint32_t)row * (LDA * 2) + (uint32_t)a_c * 16;
            const __nv_bfloat16* s = Ahi + (size_t)(m0 + row) * K + k0 + a_c * 8;
            CP16(d, s);
            CP16(d + A_BYTES, s + (Alo - Ahi));
        }
#pragma unroll
        for (int r = 0; r < 2; r++) {
            int row = b_row + r * 16;
            uint32_t d = sa + 2 * A_BYTES + (uint32_t)row * (LDB * 2) + (uint32_t)b_c * 16;
            const __nv_bfloat16* s = Bhi + (size_t)(k0 + row) * N + n0 + b_c * 8;
            CP16(d, s);
            CP16(d + B_BYTES, s + (Blo - Bhi));
        }
        CP_COMMIT();
    };

    float acc[4][4][4];
#pragma unroll
    for (int i = 0; i < 4; i++)
#pragma unroll
        for (int j = 0; j < 4; j++)
#pragma unroll
            for (int q = 0; q < 4; q++) acc[i][j][q] = 0.f;

    // per-thread ldmatrix base offsets (bf16 element units)
    const int a_base = (wm * 64 + (lane & 15)) * LDA + ((lane >> 4) << 3);
    const int b_base = (lane & 15) * LDB + wn * 32 + ((lane >> 4) << 3);

    issue(0);
    for (int c = 0; c < NC; c++) {
        if (c + 1 < NC) { issue(c + 1); CP_WAIT1(); } else { CP_WAIT0(); }
        __syncthreads();
        const uint32_t sa  = sb + (uint32_t)(c & 1) * STAGE;
        const uint32_t sal = sa + A_BYTES;
        const uint32_t sbh = sa + 2 * A_BYTES;
        const uint32_t sbl = sbh + B_BYTES;

#pragma unroll
        for (int step = 0; step < 2; step++) {
            uint32_t ah[4][4], al[4][4];
            uint32_t bh[4][2], bl[4][2];
#pragma unroll
            for (int t = 0; t < 4; t++) {
                uint32_t off = (uint32_t)(a_base + t * 16 * LDA + step * 16) * 2;
                ldsm_x4(ah[t], sa + off);
                ldsm_x4(al[t], sal + off);
            }
#pragma unroll
            for (int p = 0; p < 2; p++) {
                uint32_t off = (uint32_t)(b_base + step * 16 * LDB + p * 16) * 2;
                uint32_t r[4], rl[4];
                ldsm_x4_t(r,  sbh + off);
                ldsm_x4_t(rl, sbl + off);
                bh[2*p][0] = r[0];  bh[2*p][1] = r[1];
                bh[2*p+1][0] = r[2]; bh[2*p+1][1] = r[3];
                bl[2*p][0] = rl[0]; bl[2*p][1] = rl[1];
                bl[2*p+1][0] = rl[2]; bl[2*p+1][1] = rl[3];
            }
#pragma unroll
            for (int t = 0; t < 4; t++)
#pragma unroll
                for (int nn = 0; nn < 4; nn++) {
                    mma_bf16(acc[t][nn], ah[t], bh[nn][0], bh[nn][1]);  // hi*hi
                    mma_bf16(acc[t][nn], ah[t], bl[nn][0], bl[nn][1]);  // hi*lo
                    mma_bf16(acc[t][nn], al[t], bh[nn][0], bh[nn][1]);  // lo*hi
                }
        }
        __syncthreads();
    }

    // epilogue: bias + store (float2 per half-tile row)
    const int grow = lane >> 2;
    const int gcol = (lane & 3) * 2;
#pragma unroll
    for (int nn = 0; nn < 4; nn++) {
        int col = n0 + wn * 32 + nn * 8 + gcol;
        float2 bv = *(const float2*)&bias[col];
#pragma unroll
        for (int t = 0; t < 4; t++) {
            int row0 = m0 + wm * 64 + t * 16 + grow;
            float2 o0 = {acc[t][nn][0] + bv.x, acc[t][nn][1] + bv.y};
            float2 o1 = {acc[t][nn][2] + bv.x, acc[t][nn][3] + bv.y};
            *(float2*)&C[(size_t)row0 * N + col] = o0;
            *(float2*)&C[(size_t)(row0 + 8) * N + col] = o1;
        }
    }
}

// ---------------------------------------------------------------------------
// Flash attention (fp32, causal). One CTA per (b, h, 64-row q tile).
// Emits bf16 hi/lo split (input for the proj GEMM).
// ---------------------------------------------------------------------------
#define LDP 68

__global__ __launch_bounds__(256) void attn_kernel(const float* __restrict__ qkv,
                                                   __nv_bfloat16* __restrict__ out_hi,
                                                   __nv_bfloat16* __restrict__ out_lo)
{
    extern __shared__ float sm[];
    float* Qs = sm;
    float* Ks = sm + 64 * LDP;
    float* Vs = sm + 2 * 64 * LDP;
    float* Ps = sm + 3 * 64 * LDP;

    const int tid = threadIdx.x;
    const int tx  = tid & 15;
    const int ty  = tid >> 4;
    const int qt  = blockIdx.x;
    const int h   = blockIdx.y;
    const int b   = blockIdx.z;
    const int q0  = qt * 64;

#pragma unroll
    for (int r = 0; r < 4; r++) {
        int e  = tid + r * 256;
        int m  = e >> 4;
        int dg = (e & 15) << 2;
        const float* p = qkv + (size_t)(b * Sn + q0 + m) * QKVROW + h * HDn + dg;
        *(float4*)&Qs[m * LDP + dg] = *(const float4*)p;
    }

    float o[4][4];
    float mr[4], lr[4];
#pragma unroll
    for (int i = 0; i < 4; i++) {
        mr[i] = -INFINITY; lr[i] = 0.f;
#pragma unroll
        for (int j = 0; j < 4; j++) o[i][j] = 0.f;
    }

    for (int kt = 0; kt <= qt; kt++) {
        __syncthreads();
#pragma unroll
        for (int r = 0; r < 4; r++) {
            int e  = tid + r * 256;
            int n  = e >> 4;
            int dg = (e & 15) << 2;
            const float* p = qkv + (size_t)(b * Sn + kt * 64 + n) * QKVROW + HHD + h * HDn + dg;
            float4 kv = *(const float4*)p;
            Ks[(dg + 0) * LDP + n] = kv.x;
            Ks[(dg + 1) * LDP + n] = kv.y;
            Ks[(dg + 2) * LDP + n] = kv.z;
            Ks[(dg + 3) * LDP + n] = kv.w;
            float4 vv = *(const float4*)(p + HHD);
            *(float4*)&Vs[n * LDP + dg] = vv;
        }
        __syncthreads();

        float s[4][4];
#pragma unroll
        for (int i = 0; i < 4; i++)
#pragma unroll
            for (int j = 0; j < 4; j++) s[i][j] = 0.f;

#pragma unroll 4
        for (int d = 0; d < 64; d++) {
            float4 kf = *(const float4*)&Ks[d * LDP + tx * 4];
#pragma unroll
            for (int i = 0; i < 4; i++) {
                float qv = Qs[(ty * 4 + i) * LDP + d];
                s[i][0] = fmaf(qv, kf.x, s[i][0]);
                s[i][1] = fmaf(qv, kf.y, s[i][1]);
                s[i][2] = fmaf(qv, kf.z, s[i][2]);
                s[i][3] = fmaf(qv, kf.w, s[i][3]);
            }
        }

        const float scale = 0.125f;
        if (kt == qt) {
#pragma unroll
            for (int i = 0; i < 4; i++) {
                int qg = ty * 4 + i;
#pragma unroll
                for (int j = 0; j < 4; j++) {
                    int kg = tx * 4 + j;
                    s[i][j] = (kg <= qg) ? s[i][j] * scale : -1e30f;
                }
            }
        } else {
#pragma unroll
            for (int i = 0; i < 4; i++)
#pragma unroll
                for (int j = 0; j < 4; j++) s[i][j] *= scale;
        }

#pragma unroll
        for (int i = 0; i < 4; i++) {
            float tm = fmaxf(fmaxf(s[i][0], s[i][1]), fmaxf(s[i][2], s[i][3]));
#pragma unroll
            for (int off = 8; off > 0; off >>= 1)
                tm = fmaxf(tm, __shfl_xor_sync(0xffffffffu, tm, off));
            float mnew = fmaxf(mr[i], tm);
            float c = __expf(mr[i] - mnew);
            mr[i] = mnew;
            float rs = 0.f;
#pragma unroll
            for (int j = 0; j < 4; j++) {
                s[i][j] = __expf(s[i][j] - mnew);
                rs += s[i][j];
            }
#pragma unroll
            for (int off = 8; off > 0; off >>= 1)
                rs += __shfl_xor_sync(0xffffffffu, rs, off);
            lr[i] = lr[i] * c + rs;
#pragma unroll
            for (int j = 0; j < 4; j++) o[i][j] *= c;
        }

#pragma unroll
        for (int i = 0; i < 4; i++)
            *(float4*)&Ps[(ty * 4 + i) * LDP + tx * 4] =
                make_float4(s[i][0], s[i][1], s[i][2], s[i][3]);
        __syncthreads();

#pragma unroll 4
        for (int n = 0; n < 64; n++) {
            float4 vf = *(const float4*)&Vs[n * LDP + tx * 4];
#pragma unroll
            for (int i = 0; i < 4; i++) {
                float pv = Ps[(ty * 4 + i) * LDP + n];
                o[i][0] = fmaf(pv, vf.x, o[i][0]);
                o[i][1] = fmaf(pv, vf.y, o[i][1]);
                o[i][2] = fmaf(pv, vf.z, o[i][2]);
                o[i][3] = fmaf(pv, vf.w, o[i][3]);
            }
        }
    }

#pragma unroll
    for (int i = 0; i < 4; i++) {
        float inv = 1.f / lr[i];
        size_t base = (size_t)(b * Sn + q0 + ty * 4 + i) * HHD + h * HDn + tx * 4;
        float v0 = o[i][0] * inv, v1 = o[i][1] * inv;
        float v2 = o[i][2] * inv, v3 = o[i][3] * inv;
        __nv_bfloat16 h0 = __float2bfloat16(v0), h1 = __float2bfloat16(v1);
        __nv_bfloat16 h2 = __float2bfloat16(v2), h3 = __float2bfloat16(v3);
        __nv_bfloat162 ph0 = {h0, h1}, ph1 = {h2, h3};
        __nv_bfloat162 pl0 = {__float2bfloat16(v0 - __bfloat162float(h0)),
                              __float2bfloat16(v1 - __bfloat162float(h1))};
        __nv_bfloat162 pl1 = {__float2bfloat16(v2 - __bfloat162float(h2)),
                              __float2bfloat16(v3 - __bfloat162float(h3))};
        *(__nv_bfloat162*)&out_hi[base]     = ph0;
        *(__nv_bfloat162*)&out_hi[base + 2] = ph1;
        *(__nv_bfloat162*)&out_lo[base]     = pl0;
        *(__nv_bfloat162*)&out_lo[base + 2] = pl1;
    }
}

// ---------------------------------------------------------------------------
extern "C" void kernel_launch(void* const* d_in, const int* in_sizes, int n_in,
                              void* d_out, int out_size)
{
    const float* x      = (const float*)d_in[0];
    const float* w_qkv  = (const float*)d_in[1];
    const float* b_qkv  = (const float*)d_in[2];
    const float* w_proj = (const float*)d_in[3];
    const float* b_proj = (const float*)d_in[4];
    float* out = (float*)d_out;

    float* qkv;
    __nv_bfloat16 *xhi, *xlo, *wqh, *wql, *wph, *wpl, *ath, *atl;
    cudaGetSymbolAddress((void**)&qkv, g_qkv);
    cudaGetSymbolAddress((void**)&xhi, g_xhi);
    cudaGetSymbolAddress((void**)&xlo, g_xlo);
    cudaGetSymbolAddress((void**)&wqh, g_wqkv_hi);
    cudaGetSymbolAddress((void**)&wql, g_wqkv_lo);
    cudaGetSymbolAddress((void**)&wph, g_wproj_hi);
    cudaGetSymbolAddress((void**)&wpl, g_wproj_lo);
    cudaGetSymbolAddress((void**)&ath, g_att_hi);
    cudaGetSymbolAddress((void**)&atl, g_att_lo);

    cudaFuncSetAttribute(gemm_bf16x3_kernel,
                         cudaFuncAttributeMaxDynamicSharedMemorySize, SMEM_G);
    const int smem_a = 4 * 64 * LDP * (int)sizeof(float);
    cudaFuncSetAttribute(attn_kernel,
                         cudaFuncAttributeMaxDynamicSharedMemorySize, smem_a);

    // prep: bf16 hi/lo splits (natural layouts, no transpose needed)
    split_bf16_kernel<<<(Mrows * Dn) / 4 / 256, 256>>>(x, xhi, xlo);
    split_bf16_kernel<<<(Dn * QKVROW) / 4 / 256, 256>>>(w_qkv, wqh, wql);
    split_bf16_kernel<<<(HHD * Dn) / 4 / 256, 256>>>(w_proj, wph, wpl);

    // 1) QKV GEMM: [8192,1024] @ [1024,3072] + bias
    gemm_bf16x3_kernel<<<dim3(QKVROW / BN, Mrows / BM), 256, SMEM_G>>>(
        xhi, xlo, wqh, wql, b_qkv, qkv, Mrows, QKVROW, Dn);

    // 2) causal flash attention (fp32), emits bf16 hi/lo split
    attn_kernel<<<dim3(Sn / 64, Hn, Bn), 256, smem_a>>>(qkv, ath, atl);

    // 3) proj GEMM: [8192,1024] @ [1024,1024] + bias
    gemm_bf16x3_kernel<<<dim3(Dn / BN, Mrows / BM), 256, SMEM_G>>>(
        ath, atl, wph, wpl, b_proj, out, Mrows, Dn, HHD);
}

// round 4
// speedup vs baseline: 2.6833x; 1.9153x over previous
#include <cuda_runtime.h>
#include <cuda_bf16.h>
#include <math.h>
#include <stdint.h>

// Problem constants
#define Bn   4
#define Sn   2048
#define Dn   1024
#define Hn   16
#define HDn  64
#define HHD  (Hn*HDn)      // 1024
#define QKVROW (3*HHD)     // 3072
#define Mrows (Bn*Sn)      // 8192

// ---------------- scratch (allocation-free device globals) ----------------
__device__ __align__(128) __nv_bfloat16 g_xhi[(size_t)Mrows * Dn];
__device__ __align__(128) __nv_bfloat16 g_xlo[(size_t)Mrows * Dn];
__device__ __align__(128) __nv_bfloat16 g_wqkv_hi[(size_t)Dn * QKVROW];   // [K][N]
__device__ __align__(128) __nv_bfloat16 g_wqkv_lo[(size_t)Dn * QKVROW];
__device__ __align__(128) __nv_bfloat16 g_wproj_hi[(size_t)HHD * Dn];     // [K][N]
__device__ __align__(128) __nv_bfloat16 g_wproj_lo[(size_t)HHD * Dn];
// Q/K/V head-major [B][H][S][64], bf16 hi/lo (Q pre-scaled by 0.125)
__device__ __align__(128) __nv_bfloat16 g_q_hi[(size_t)Bn * Hn * Sn * HDn];
__device__ __align__(128) __nv_bfloat16 g_q_lo[(size_t)Bn * Hn * Sn * HDn];
__device__ __align__(128) __nv_bfloat16 g_k_hi[(size_t)Bn * Hn * Sn * HDn];
__device__ __align__(128) __nv_bfloat16 g_k_lo[(size_t)Bn * Hn * Sn * HDn];
__device__ __align__(128) __nv_bfloat16 g_v_hi[(size_t)Bn * Hn * Sn * HDn];
__device__ __align__(128) __nv_bfloat16 g_v_lo[(size_t)Bn * Hn * Sn * HDn];
__device__ __align__(128) __nv_bfloat16 g_att_hi[(size_t)Mrows * HHD];
__device__ __align__(128) __nv_bfloat16 g_att_lo[(size_t)Mrows * HHD];

// ---------------- PTX helpers ----------------
__device__ __forceinline__ uint32_t smem_u32(const void* p) {
    uint32_t a;
    asm("{ .reg .u64 t; cvta.to.shared.u64 t, %1; cvt.u32.u64 %0, t; }" : "=r"(a) : "l"(p));
    return a;
}
#define CP16(s, g) asm volatile("cp.async.cg.shared.global [%0], [%1], 16;" :: "r"(s), "l"(g))
#define CP_COMMIT() asm volatile("cp.async.commit_group;" ::: "memory")
#define CP_WAIT1()  asm volatile("cp.async.wait_group 1;" ::: "memory")
#define CP_WAIT0()  asm volatile("cp.async.wait_group 0;" ::: "memory")

__device__ __forceinline__ void ldsm_x4(uint32_t (&r)[4], uint32_t addr) {
    asm volatile("ldmatrix.sync.aligned.m8n8.x4.shared.b16 {%0,%1,%2,%3}, [%4];"
                 : "=r"(r[0]), "=r"(r[1]), "=r"(r[2]), "=r"(r[3]) : "r"(addr));
}
__device__ __forceinline__ void ldsm_x4_t(uint32_t (&r)[4], uint32_t addr) {
    asm volatile("ldmatrix.sync.aligned.m8n8.x4.trans.shared.b16 {%0,%1,%2,%3}, [%4];"
                 : "=r"(r[0]), "=r"(r[1]), "=r"(r[2]), "=r"(r[3]) : "r"(addr));
}
__device__ __forceinline__ void mma_bf16(float (&c)[4], const uint32_t (&a)[4],
                                         uint32_t b0, uint32_t b1) {
    asm volatile(
        "mma.sync.aligned.m16n8k16.row.col.f32.bf16.bf16.f32 "
        "{%0,%1,%2,%3}, {%4,%5,%6,%7}, {%8,%9}, {%0,%1,%2,%3};"
        : "+f"(c[0]), "+f"(c[1]), "+f"(c[2]), "+f"(c[3])
        : "r"(a[0]), "r"(a[1]), "r"(a[2]), "r"(a[3]), "r"(b0), "r"(b1));
}
// pack two f32 into bf16x2: low half = lo, high half = hi
__device__ __forceinline__ uint32_t pack_bf16(float lo, float hi) {
    uint32_t r;
    asm("cvt.rn.bf16x2.f32 %0, %1, %2;" : "=r"(r) : "f"(hi), "f"(lo));
    return r;
}
__device__ __forceinline__ float bf16_val(float x) {
    return __bfloat162float(__float2bfloat16(x));
}
// XOR-swizzled smem offset: 128B rows, 16B chunks, conflict-free ldmatrix
#define SWZ(row, c) ((uint32_t)((row) * 128 + (((c) ^ ((row) & 7)) << 4)))

// ---------------- bf16 split prep ----------------
__global__ __launch_bounds__(256) void split_bf16_kernel(
    const float* __restrict__ in, __nv_bfloat16* __restrict__ hi,
    __nv_bfloat16* __restrict__ lo)
{
    int i = blockIdx.x * 256 + threadIdx.x;   // float4 index
    float4 v = ((const float4*)in)[i];
    __nv_bfloat16 h0 = __float2bfloat16(v.x);
    __nv_bfloat16 h1 = __float2bfloat16(v.y);
    __nv_bfloat16 h2 = __float2bfloat16(v.z);
    __nv_bfloat16 h3 = __float2bfloat16(v.w);
    __nv_bfloat162 ph0 = {h0, h1}, ph1 = {h2, h3};
    __nv_bfloat162 pl0 = {__float2bfloat16(v.x - __bfloat162float(h0)),
                          __float2bfloat16(v.y - __bfloat162float(h1))};
    __nv_bfloat162 pl1 = {__float2bfloat16(v.z - __bfloat162float(h2)),
                          __float2bfloat16(v.w - __bfloat162float(h3))};
    ((__nv_bfloat162*)hi)[i * 2 + 0] = ph0;
    ((__nv_bfloat162*)hi)[i * 2 + 1] = ph1;
    ((__nv_bfloat162*)lo)[i * 2 + 0] = pl0;
    ((__nv_bfloat162*)lo)[i * 2 + 1] = pl1;
}

// ---------------- bf16 split-3MMA tensor-core GEMM ----------------
#define BM 128
#define BN 128
#define BKc 32
#define LDA 40
#define LDB 136
#define A_BYTES (BM * LDA * 2)
#define B_BYTES (BKc * LDB * 2)
#define STAGE   (2 * A_BYTES + 2 * B_BYTES)
#define SMEM_G  (2 * STAGE)

// mode 0: C = fp32 out + bias (proj). mode 1: scatter to q/k/v bf16 hi/lo arrays.
__global__ __launch_bounds__(256) void gemm_bf16x3_kernel(
    const __nv_bfloat16* __restrict__ Ahi, const __nv_bfloat16* __restrict__ Alo,
    const __nv_bfloat16* __restrict__ Bhi, const __nv_bfloat16* __restrict__ Blo,
    const float* __restrict__ bias, float* __restrict__ C,
    __nv_bfloat16* __restrict__ qh, __nv_bfloat16* __restrict__ ql,
    __nv_bfloat16* __restrict__ kh, __nv_bfloat16* __restrict__ kl,
    __nv_bfloat16* __restrict__ vh, __nv_bfloat16* __restrict__ vl,
    int M, int N, int K, int mode)
{
    extern __shared__ char smg[];
    const uint32_t sb = smem_u32(smg);
    const int tid  = threadIdx.x;
    const int wid  = tid >> 5;
    const int lane = tid & 31;
    const int wm   = wid & 1;
    const int wn   = wid >> 1;
    const int n0   = blockIdx.x * BN;
    const int m0   = blockIdx.y * BM;
    const int NC   = K / BKc;

    const int a_row = tid >> 2, a_c = tid & 3;
    const int b_row = tid >> 4, b_c = tid & 15;

    auto issue = [&](int c) {
        const uint32_t sa = sb + (uint32_t)(c & 1) * STAGE;
        const int k0 = c * BKc;
#pragma unroll
        for (int r = 0; r < 2; r++) {
            int row = a_row + r * 64;
            uint32_t d = sa + (uint32_t)row * (LDA * 2) + (uint32_t)a_c * 16;
            const __nv_bfloat16* s = Ahi + (size_t)(m0 + row) * K + k0 + a_c * 8;
            CP16(d, s);
            CP16(d + A_BYTES, s + (Alo - Ahi));
        }
#pragma unroll
        for (int r = 0; r < 2; r++) {
            int row = b_row + r * 16;
            uint32_t d = sa + 2 * A_BYTES + (uint32_t)row * (LDB * 2) + (uint32_t)b_c * 16;
            const __nv_bfloat16* s = Bhi + (size_t)(k0 + row) * N + n0 + b_c * 8;
            CP16(d, s);
            CP16(d + B_BYTES, s + (Blo - Bhi));
        }
        CP_COMMIT();
    };

    float acc[4][4][4];
#pragma unroll
    for (int i = 0; i < 4; i++)
#pragma unroll
        for (int j = 0; j < 4; j++)
#pragma unroll
            for (int q = 0; q < 4; q++) acc[i][j][q] = 0.f;

    const int a_base = (wm * 64 + (lane & 15)) * LDA + ((lane >> 4) << 3);
    const int b_base = (lane & 15) * LDB + wn * 32 + ((lane >> 4) << 3);

    issue(0);
    for (int c = 0; c < NC; c++) {
        if (c + 1 < NC) { issue(c + 1); CP_WAIT1(); } else { CP_WAIT0(); }
        __syncthreads();
        const uint32_t sa  = sb + (uint32_t)(c & 1) * STAGE;
        const uint32_t sal = sa + A_BYTES;
        const uint32_t sbh = sa + 2 * A_BYTES;
        const uint32_t sbl = sbh + B_BYTES;

#pragma unroll
        for (int step = 0; step < 2; step++) {
            uint32_t ah[4][4], al[4][4];
            uint32_t bh[4][2], bl[4][2];
#pragma unroll
            for (int t = 0; t < 4; t++) {
                uint32_t off = (uint32_t)(a_base + t * 16 * LDA + step * 16) * 2;
                ldsm_x4(ah[t], sa + off);
                ldsm_x4(al[t], sal + off);
            }
#pragma unroll
            for (int p = 0; p < 2; p++) {
                uint32_t off = (uint32_t)(b_base + step * 16 * LDB + p * 16) * 2;
                uint32_t r[4], rl[4];
                ldsm_x4_t(r,  sbh + off);
                ldsm_x4_t(rl, sbl + off);
                bh[2*p][0] = r[0];  bh[2*p][1] = r[1];
                bh[2*p+1][0] = r[2]; bh[2*p+1][1] = r[3];
                bl[2*p][0] = rl[0]; bl[2*p][1] = rl[1];
                bl[2*p+1][0] = rl[2]; bl[2*p+1][1] = rl[3];
            }
#pragma unroll
            for (int t = 0; t < 4; t++)
#pragma unroll
                for (int nn = 0; nn < 4; nn++) {
                    mma_bf16(acc[t][nn], ah[t], bh[nn][0], bh[nn][1]);
                    mma_bf16(acc[t][nn], ah[t], bl[nn][0], bl[nn][1]);
                    mma_bf16(acc[t][nn], al[t], bh[nn][0], bh[nn][1]);
                }
        }
        __syncthreads();
    }

    const int grow = lane >> 2;
    const int gcol = (lane & 3) * 2;

    if (mode == 0) {
#pragma unroll
        for (int nn = 0; nn < 4; nn++) {
            int col = n0 + wn * 32 + nn * 8 + gcol;
            float2 bv = *(const float2*)&bias[col];
#pragma unroll
            for (int t = 0; t < 4; t++) {
                int row0 = m0 + wm * 64 + t * 16 + grow;
                float2 o0 = {acc[t][nn][0] + bv.x, acc[t][nn][1] + bv.y};
                float2 o1 = {acc[t][nn][2] + bv.x, acc[t][nn][3] + bv.y};
                *(float2*)&C[(size_t)row0 * N + col] = o0;
                *(float2*)&C[(size_t)(row0 + 8) * N + col] = o1;
            }
        }
    } else {
        // scatter to [B][H][S][64] bf16 hi/lo; q pre-scaled by 0.125
        const int colb = n0 + wn * 32;
        const int t3 = colb >> 10;               // 0=q 1=k 2=v (CTA-uniform)
        const int hh = (colb & 1023) >> 6;       // warp-uniform head
        __nv_bfloat16 *ph, *pl;
        if (t3 == 0)      { ph = qh; pl = ql; }
        else if (t3 == 1) { ph = kh; pl = kl; }
        else              { ph = vh; pl = vl; }
        const float qsc = (t3 == 0) ? 0.125f : 1.f;
        const int bidx = m0 >> 11;
#pragma unroll
        for (int nn = 0; nn < 4; nn++) {
            int col = colb + nn * 8 + gcol;
            int d = col & 63;
            float2 bv = *(const float2*)&bias[col];
#pragma unroll
            for (int t = 0; t < 4; t++) {
                int row0 = m0 + wm * 64 + t * 16 + grow;
                int s = row0 & 2047;
                size_t base = ((size_t)(bidx * Hn + hh) * Sn + s) * 64 + d;
                float vx = (acc[t][nn][0] + bv.x) * qsc;
                float vy = (acc[t][nn][1] + bv.y) * qsc;
                *(uint32_t*)&ph[base] = pack_bf16(vx, vy);
                *(uint32_t*)&pl[base] = pack_bf16(vx - bf16_val(vx), vy - bf16_val(vy));
                float vx2 = (acc[t][nn][2] + bv.x) * qsc;
                float vy2 = (acc[t][nn][3] + bv.y) * qsc;
                size_t base8 = base + 8 * 64;
                *(uint32_t*)&ph[base8] = pack_bf16(vx2, vy2);
                *(uint32_t*)&pl[base8] = pack_bf16(vx2 - bf16_val(vx2), vy2 - bf16_val(vy2));
            }
        }
    }
}

// ---------------------------------------------------------------------------
// Tensor-core flash attention. CTA = 128 q rows of one (b,h); 8 warps x 16 rows.
// 64-key tiles, double-buffered cp.async; 3-MMA bf16 split throughout.
// smem: Q hi/lo 32KB + 2 stages x (K hi/lo + V hi/lo) 32KB = 96KB.
// ---------------------------------------------------------------------------
#define ASMEM (32768 + 2 * 32768)

__global__ __launch_bounds__(256, 2) void attn_mma_kernel(
    const __nv_bfloat16* __restrict__ Qh, const __nv_bfloat16* __restrict__ Ql,
    const __nv_bfloat16* __restrict__ Kh, const __nv_bfloat16* __restrict__ Kl,
    const __nv_bfloat16* __restrict__ Vh, const __nv_bfloat16* __restrict__ Vl,
    __nv_bfloat16* __restrict__ out_hi, __nv_bfloat16* __restrict__ out_lo)
{
    extern __shared__ char sma[];
    const uint32_t sb  = smem_u32(sma);
    const uint32_t sQh = sb, sQl = sb + 16384;
    const int tid = threadIdx.x, wid = tid >> 5, lane = tid & 31;
    const int qt = blockIdx.x, h = blockIdx.y, b = blockIdx.z;
    const int q0 = qt * 128;
    const size_t head = ((size_t)(b * Hn + h)) * Sn * 64;

    // load Q tile (hi+lo) once
    for (int i = tid; i < 1024; i += 256) {
        int row = i >> 3, c = i & 7;
        uint32_t d = SWZ(row, c);
        const size_t g = head + (size_t)(q0 + row) * 64 + c * 8;
        CP16(sQh + d, Qh + g);
        CP16(sQl + d, Ql + g);
    }
    CP_COMMIT();

    auto issue_kv = [&](int kt) {
        uint32_t st = sb + 32768 + (uint32_t)(kt & 1) * 32768;
        const int k0 = kt * 64;
        for (int i = tid; i < 512; i += 256) {
            int row = i >> 3, c = i & 7;
            uint32_t d = SWZ(row, c);
            size_t g = head + (size_t)(k0 + row) * 64 + c * 8;
            CP16(st + d,         Kh + g);
            CP16(st + 8192 + d,  Kl + g);
            CP16(st + 16384 + d, Vh + g);
            CP16(st + 24576 + d, Vl + g);
        }
        CP_COMMIT();
    };

    float oacc[8][4];
#pragma unroll
    for (int j = 0; j < 8; j++)
#pragma unroll
        for (int q = 0; q < 4; q++) oacc[j][q] = 0.f;
    float m[2] = {-1e30f, -1e30f}, l[2] = {0.f, 0.f};

    const int nkt = 2 * qt + 2;
    issue_kv(0);

    // per-lane fragment geometry
    const int qr      = wid * 16 + (lane & 15);
    const int qc_add  = (lane >> 4);
    const int kr_base = ((lane >> 4) << 3) + (lane & 7);
    const int kc_add  = ((lane >> 3) & 1);
    const int vr      = (lane & 15);

    for (int c = 0; c < nkt; c++) {
        if (c + 1 < nkt) { issue_kv(c + 1); CP_WAIT1(); } else { CP_WAIT0(); }
        __syncthreads();
        const uint32_t st = sb + 32768 + (uint32_t)(c & 1) * 32768;
        const int k0 = c * 64;

        // ---- S = Q K^T (3-MMA split) ----
        float sacc[8][4];
#pragma unroll
        for (int j = 0; j < 8; j++)
#pragma unroll
            for (int q = 0; q < 4; q++) sacc[j][q] = 0.f;

#pragma unroll
        for (int ks = 0; ks < 4; ks++) {
            uint32_t qoff = SWZ(qr, 2 * ks + qc_add);
            uint32_t qh4[4], ql4[4];
            ldsm_x4(qh4, sQh + qoff);
            ldsm_x4(ql4, sQl + qoff);
#pragma unroll
            for (int kg = 0; kg < 4; kg++) {
                int krow = kg * 16 + kr_base;
                uint32_t koff = SWZ(krow, 2 * ks + kc_add);
                uint32_t kh4[4], kl4[4];
                ldsm_x4(kh4, st + koff);
                ldsm_x4(kl4, st + 8192 + koff);
                mma_bf16(sacc[2*kg],   qh4, kh4[0], kh4[1]);
                mma_bf16(sacc[2*kg],   qh4, kl4[0], kl4[1]);
                mma_bf16(sacc[2*kg],   ql4, kh4[0], kh4[1]);
                mma_bf16(sacc[2*kg+1], qh4, kh4[2], kh4[3]);
                mma_bf16(sacc[2*kg+1], qh4, kl4[2], kl4[3]);
                mma_bf16(sacc[2*kg+1], ql4, kh4[2], kh4[3]);
            }
        }

        // ---- causal mask (Q pre-scaled; raw scores compare-only) ----
        const int r0g = q0 + wid * 16 + (lane >> 2);
        if (k0 + 63 > q0 + wid * 16) {
#pragma unroll
            for (int j = 0; j < 8; j++) {
                int key = k0 + 8 * j + (lane & 3) * 2;
                if (key     > r0g)     sacc[j][0] = -1e30f;
                if (key + 1 > r0g)     sacc[j][1] = -1e30f;
                if (key     > r0g + 8) sacc[j][2] = -1e30f;
                if (key + 1 > r0g + 8) sacc[j][3] = -1e30f;
            }
        }

        // ---- online softmax per row-group ----
#pragma unroll
        for (int rg = 0; rg < 2; rg++) {
            float tm = -1e30f;
#pragma unroll
            for (int j = 0; j < 8; j++)
                tm = fmaxf(tm, fmaxf(sacc[j][2*rg], sacc[j][2*rg+1]));
            tm = fmaxf(tm, __shfl_xor_sync(0xffffffffu, tm, 1));
            tm = fmaxf(tm, __shfl_xor_sync(0xffffffffu, tm, 2));
            float mnew = fmaxf(m[rg], tm);
            float corr = __expf(m[rg] - mnew);
            m[rg] = mnew;
            float rs = 0.f;
#pragma unroll
            for (int j = 0; j < 8; j++) {
                float e0 = __expf(sacc[j][2*rg]   - mnew);
                float e1 = __expf(sacc[j][2*rg+1] - mnew);
                sacc[j][2*rg] = e0; sacc[j][2*rg+1] = e1;
                rs += e0 + e1;
            }
            rs += __shfl_xor_sync(0xffffffffu, rs, 1);
            rs += __shfl_xor_sync(0xffffffffu, rs, 2);
            l[rg] = l[rg] * corr + rs;
#pragma unroll
            for (int j = 0; j < 8; j++) {
                oacc[j][2*rg]   *= corr;
                oacc[j][2*rg+1] *= corr;
            }
        }

        // ---- O += P V (3-MMA split, P packed in-register) ----
#pragma unroll
        for (int t = 0; t < 4; t++) {
            uint32_t phi[4], plo[4];
#pragma unroll
            for (int half = 0; half < 2; half++) {
                const float p0 = sacc[2*t + half][0], p1 = sacc[2*t + half][1];
                const float p2 = sacc[2*t + half][2], p3 = sacc[2*t + half][3];
                phi[2*half]     = pack_bf16(p0, p1);
                phi[2*half + 1] = pack_bf16(p2, p3);
                plo[2*half]     = pack_bf16(p0 - bf16_val(p0), p1 - bf16_val(p1));
                plo[2*half + 1] = pack_bf16(p2 - bf16_val(p2), p3 - bf16_val(p3));
            }
            // NOTE: phi/plo must be ordered {a0,a1,a2,a3} = {frag2t.c01, frag2t.c23,
            // frag2t+1.c01, frag2t+1.c23} — half loop gives exactly that.
            int vrow = t * 16 + vr;
#pragma unroll
            for (int p = 0; p < 4; p++) {
                uint32_t voff = SWZ(vrow, 2 * p + qc_add);
                uint32_t vh4[4], vl4[4];
                ldsm_x4_t(vh4, st + 16384 + voff);
                ldsm_x4_t(vl4, st + 24576 + voff);
                mma_bf16(oacc[2*p],   phi, vh4[0], vh4[1]);
                mma_bf16(oacc[2*p],   phi, vl4[0], vl4[1]);
                mma_bf16(oacc[2*p],   plo, vh4[0], vh4[1]);
                mma_bf16(oacc[2*p+1], phi, vh4[2], vh4[3]);
                mma_bf16(oacc[2*p+1], phi, vl4[2], vl4[3]);
                mma_bf16(oacc[2*p+1], plo, vh4[2], vh4[3]);
            }
        }
        __syncthreads();
    }

    // ---- normalize + bf16 hi/lo split store to [row=(b,s)][h*64+d] ----
    const float inv0 = 1.f / l[0], inv1 = 1.f / l[1];
    const int s0 = q0 + wid * 16 + (lane >> 2);
#pragma unroll
    for (int j = 0; j < 8; j++) {
        int dcol = h * 64 + 8 * j + (lane & 3) * 2;
        size_t i0 = (size_t)(b * Sn + s0) * HHD + dcol;
        size_t i1 = i0 + (size_t)8 * HHD;
        float vx = oacc[j][0] * inv0, vy = oacc[j][1] * inv0;
        *(uint32_t*)&out_hi[i0] = pack_bf16(vx, vy);
        *(uint32_t*)&out_lo[i0] = pack_bf16(vx - bf16_val(vx), vy - bf16_val(vy));
        float v2 = oacc[j][2] * inv1, v3 = oacc[j][3] * inv1;
        *(uint32_t*)&out_hi[i1] = pack_bf16(v2, v3);
        *(uint32_t*)&out_lo[i1] = pack_bf16(v2 - bf16_val(v2), v3 - bf16_val(v3));
    }
}

// ---------------------------------------------------------------------------
extern "C" void kernel_launch(void* const* d_in, const int* in_sizes, int n_in,
                              void* d_out, int out_size)
{
    const float* x      = (const float*)d_in[0];
    const float* w_qkv  = (const float*)d_in[1];
    const float* b_qkv  = (const float*)d_in[2];
    const float* w_proj = (const float*)d_in[3];
    const float* b_proj = (const float*)d_in[4];
    float* out = (float*)d_out;

    __nv_bfloat16 *xhi, *xlo, *wqh, *wql, *wph, *wpl, *ath, *atl;
    __nv_bfloat16 *qh, *ql, *kh, *kl, *vh, *vl;
    cudaGetSymbolAddress((void**)&xhi, g_xhi);
    cudaGetSymbolAddress((void**)&xlo, g_xlo);
    cudaGetSymbolAddress((void**)&wqh, g_wqkv_hi);
    cudaGetSymbolAddress((void**)&wql, g_wqkv_lo);
    cudaGetSymbolAddress((void**)&wph, g_wproj_hi);
    cudaGetSymbolAddress((void**)&wpl, g_wproj_lo);
    cudaGetSymbolAddress((void**)&ath, g_att_hi);
    cudaGetSymbolAddress((void**)&atl, g_att_lo);
    cudaGetSymbolAddress((void**)&qh, g_q_hi);
    cudaGetSymbolAddress((void**)&ql, g_q_lo);
    cudaGetSymbolAddress((void**)&kh, g_k_hi);
    cudaGetSymbolAddress((void**)&kl, g_k_lo);
    cudaGetSymbolAddress((void**)&vh, g_v_hi);
    cudaGetSymbolAddress((void**)&vl, g_v_lo);

    cudaFuncSetAttribute(gemm_bf16x3_kernel,
                         cudaFuncAttributeMaxDynamicSharedMemorySize, SMEM_G);
    cudaFuncSetAttribute(attn_mma_kernel,
                         cudaFuncAttributeMaxDynamicSharedMemorySize, ASMEM);

    // prep: bf16 hi/lo splits
    split_bf16_kernel<<<(Mrows * Dn) / 4 / 256, 256>>>(x, xhi, xlo);
    split_bf16_kernel<<<(Dn * QKVROW) / 4 / 256, 256>>>(w_qkv, wqh, wql);
    split_bf16_kernel<<<(HHD * Dn) / 4 / 256, 256>>>(w_proj, wph, wpl);

    // 1) QKV GEMM -> head-major bf16 hi/lo q/k/v (q pre-scaled by 1/8)
    gemm_bf16x3_kernel<<<dim3(QKVROW / BN, Mrows / BM), 256, SMEM_G>>>(
        xhi, xlo, wqh, wql, b_qkv, nullptr,
        qh, ql, kh, kl, vh, vl, Mrows, QKVROW, Dn, 1);

    // 2) tensor-core causal flash attention -> att bf16 hi/lo
    attn_mma_kernel<<<dim3(Sn / 128, Hn, Bn), 256, ASMEM>>>(
        qh, ql, kh, kl, vh, vl, ath, atl);

    // 3) proj GEMM -> fp32 out + bias
    gemm_bf16x3_kernel<<<dim3(Dn / BN, Mrows / BM), 256, SMEM_G>>>(
        ath, atl, wph, wpl, b_proj, out,
        nullptr, nullptr, nullptr, nullptr, nullptr, nullptr,
        Mrows, Dn, HHD, 0);
}

// round 5
// speedup vs baseline: 3.7170x; 1.3852x over previous
#include <cuda_runtime.h>
#include <cuda_fp16.h>
#include <math.h>
#include <stdint.h>

// Problem constants
#define Bn   4
#define Sn   2048
#define Dn   1024
#define Hn   16
#define HDn  64
#define HHD  (Hn*HDn)      // 1024
#define QKVROW (3*HHD)     // 3072
#define Mrows (Bn*Sn)      // 8192

// ---------------- scratch (allocation-free device globals) ----------------
__device__ __align__(128) __half g_xhi[(size_t)Mrows * Dn];
__device__ __align__(128) __half g_xlo[(size_t)Mrows * Dn];
__device__ __align__(128) __half g_wqkv[(size_t)Dn * QKVROW];   // [K][N] plain fp16
__device__ __align__(128) __half g_wproj[(size_t)HHD * Dn];     // [K][N] plain fp16
// Q/K/V head-major [B][H][S][64]; Q split hi/lo (pre-scaled 0.125), K/V plain
__device__ __align__(128) __half g_q_hi[(size_t)Bn * Hn * Sn * HDn];
__device__ __align__(128) __half g_q_lo[(size_t)Bn * Hn * Sn * HDn];
__device__ __align__(128) __half g_k[(size_t)Bn * Hn * Sn * HDn];
__device__ __align__(128) __half g_v[(size_t)Bn * Hn * Sn * HDn];
__device__ __align__(128) __half g_att_hi[(size_t)Mrows * HHD];
__device__ __align__(128) __half g_att_lo[(size_t)Mrows * HHD];

// ---------------- PTX helpers ----------------
__device__ __forceinline__ uint32_t smem_u32(const void* p) {
    uint32_t a;
    asm("{ .reg .u64 t; cvta.to.shared.u64 t, %1; cvt.u32.u64 %0, t; }" : "=r"(a) : "l"(p));
    return a;
}
#define CP16(s, g) asm volatile("cp.async.cg.shared.global [%0], [%1], 16;" :: "r"(s), "l"(g))
#define CP_COMMIT() asm volatile("cp.async.commit_group;" ::: "memory")
#define CP_WAIT1()  asm volatile("cp.async.wait_group 1;" ::: "memory")
#define CP_WAIT0()  asm volatile("cp.async.wait_group 0;" ::: "memory")

__device__ __forceinline__ void ldsm_x4(uint32_t (&r)[4], uint32_t addr) {
    asm volatile("ldmatrix.sync.aligned.m8n8.x4.shared.b16 {%0,%1,%2,%3}, [%4];"
                 : "=r"(r[0]), "=r"(r[1]), "=r"(r[2]), "=r"(r[3]) : "r"(addr));
}
__device__ __forceinline__ void ldsm_x4_t(uint32_t (&r)[4], uint32_t addr) {
    asm volatile("ldmatrix.sync.aligned.m8n8.x4.trans.shared.b16 {%0,%1,%2,%3}, [%4];"
                 : "=r"(r[0]), "=r"(r[1]), "=r"(r[2]), "=r"(r[3]) : "r"(addr));
}
__device__ __forceinline__ void mma_f16(float (&c)[4], const uint32_t (&a)[4],
                                        uint32_t b0, uint32_t b1) {
    asm volatile(
        "mma.sync.aligned.m16n8k16.row.col.f32.f16.f16.f32 "
        "{%0,%1,%2,%3}, {%4,%5,%6,%7}, {%8,%9}, {%0,%1,%2,%3};"
        : "+f"(c[0]), "+f"(c[1]), "+f"(c[2]), "+f"(c[3])
        : "r"(a[0]), "r"(a[1]), "r"(a[2]), "r"(a[3]), "r"(b0), "r"(b1));
}
// pack two f32 into f16x2: low half = first arg, high half = second arg
__device__ __forceinline__ uint32_t pack_f16(float lo, float hi) {
    uint32_t r;
    asm("cvt.rn.f16x2.f32 %0, %1, %2;" : "=r"(r) : "f"(hi), "f"(lo));
    return r;
}
__device__ __forceinline__ float f16_val(float x) {
    return __half2float(__float2half(x));
}
// XOR-swizzled smem offset: 128B rows, 16B chunks, conflict-free ldmatrix
#define SWZ(row, c) ((uint32_t)((row) * 128 + (((c) ^ ((row) & 7)) << 4)))

// ---------------- prep kernels ----------------
__global__ __launch_bounds__(256) void split_f16_kernel(
    const float* __restrict__ in, __half* __restrict__ hi, __half* __restrict__ lo)
{
    int i = blockIdx.x * 256 + threadIdx.x;   // float4 index
    float4 v = ((const float4*)in)[i];
    uint32_t h0 = pack_f16(v.x, v.y);
    uint32_t h1 = pack_f16(v.z, v.w);
    uint32_t l0 = pack_f16(v.x - f16_val(v.x), v.y - f16_val(v.y));
    uint32_t l1 = pack_f16(v.z - f16_val(v.z), v.w - f16_val(v.w));
    ((uint32_t*)hi)[i * 2 + 0] = h0;
    ((uint32_t*)hi)[i * 2 + 1] = h1;
    ((uint32_t*)lo)[i * 2 + 0] = l0;
    ((uint32_t*)lo)[i * 2 + 1] = l1;
}
__global__ __launch_bounds__(256) void tof16_kernel(
    const float* __restrict__ in, __half* __restrict__ out)
{
    int i = blockIdx.x * 256 + threadIdx.x;
    float4 v = ((const float4*)in)[i];
    ((uint32_t*)out)[i * 2 + 0] = pack_f16(v.x, v.y);
    ((uint32_t*)out)[i * 2 + 1] = pack_f16(v.z, v.w);
}

// ---------------- fp16 A-split 2-MMA tensor-core GEMM ----------------
// C[M,N] = (Ahi+Alo)[M,K] @ B[K,N] + bias. CTA 128x128, BK=32, 8 warps.
#define BM 128
#define BN 128
#define BKc 32
#define LDA 40
#define LDB 136
#define A_BYTES (BM * LDA * 2)          // 10240
#define B_BYTES (BKc * LDB * 2)         // 8704
#define STAGE   (2 * A_BYTES + B_BYTES) // 29184
#define SMEM_G  (2 * STAGE)             // 58368

// mode 0: fp32 out + bias (proj). mode 1: scatter q(split,0.125x)/k/v fp16.
__global__ __launch_bounds__(256, 2) void gemm_f16s_kernel(
    const __half* __restrict__ Ahi, const __half* __restrict__ Alo,
    const __half* __restrict__ Bw,
    const float* __restrict__ bias, float* __restrict__ C,
    __half* __restrict__ qh, __half* __restrict__ ql,
    __half* __restrict__ kk, __half* __restrict__ vv,
    int M, int N, int K, int mode)
{
    extern __shared__ char smg[];
    const uint32_t sb = smem_u32(smg);
    const int tid  = threadIdx.x;
    const int wid  = tid >> 5;
    const int lane = tid & 31;
    const int wm   = wid & 1;
    const int wn   = wid >> 1;
    const int n0   = blockIdx.x * BN;
    const int m0   = blockIdx.y * BM;
    const int NC   = K / BKc;

    const int a_row = tid >> 2, a_c = tid & 3;
    const int b_row = tid >> 4, b_c = tid & 15;

    auto issue = [&](int c) {
        const uint32_t sa = sb + (uint32_t)(c & 1) * STAGE;
        const int k0 = c * BKc;
#pragma unroll
        for (int r = 0; r < 2; r++) {
            int row = a_row + r * 64;
            uint32_t d = sa + (uint32_t)row * (LDA * 2) + (uint32_t)a_c * 16;
            const __half* s = Ahi + (size_t)(m0 + row) * K + k0 + a_c * 8;
            CP16(d, s);
            CP16(d + A_BYTES, s + (Alo - Ahi));
        }
#pragma unroll
        for (int r = 0; r < 2; r++) {
            int row = b_row + r * 16;
            uint32_t d = sa + 2 * A_BYTES + (uint32_t)row * (LDB * 2) + (uint32_t)b_c * 16;
            CP16(d, Bw + (size_t)(k0 + row) * N + n0 + b_c * 8);
        }
        CP_COMMIT();
    };

    float acc[4][4][4];
#pragma unroll
    for (int i = 0; i < 4; i++)
#pragma unroll
        for (int j = 0; j < 4; j++)
#pragma unroll
            for (int q = 0; q < 4; q++) acc[i][j][q] = 0.f;

    const int a_base = (wm * 64 + (lane & 15)) * LDA + ((lane >> 4) << 3);
    const int b_base = (lane & 15) * LDB + wn * 32 + ((lane >> 4) << 3);

    issue(0);
    for (int c = 0; c < NC; c++) {
        CP_WAIT0();
        __syncthreads();
        if (c + 1 < NC) issue(c + 1);   // overlaps with compute below

        const uint32_t sa  = sb + (uint32_t)(c & 1) * STAGE;
        const uint32_t sal = sa + A_BYTES;
        const uint32_t sbw = sa + 2 * A_BYTES;

#pragma unroll
        for (int step = 0; step < 2; step++) {
            uint32_t ah[4][4], al[4][4];
            uint32_t bw[4][2];
#pragma unroll
            for (int t = 0; t < 4; t++) {
                uint32_t off = (uint32_t)(a_base + t * 16 * LDA + step * 16) * 2;
                ldsm_x4(ah[t], sa + off);
                ldsm_x4(al[t], sal + off);
            }
#pragma unroll
            for (int p = 0; p < 2; p++) {
                uint32_t off = (uint32_t)(b_base + step * 16 * LDB + p * 16) * 2;
                uint32_t r[4];
                ldsm_x4_t(r, sbw + off);
                bw[2*p][0]   = r[0]; bw[2*p][1]   = r[1];
                bw[2*p+1][0] = r[2]; bw[2*p+1][1] = r[3];
            }
#pragma unroll
            for (int t = 0; t < 4; t++)
#pragma unroll
                for (int nn = 0; nn < 4; nn++) {
                    mma_f16(acc[t][nn], ah[t], bw[nn][0], bw[nn][1]);
                    mma_f16(acc[t][nn], al[t], bw[nn][0], bw[nn][1]);
                }
        }
        __syncthreads();   // guard stage reuse: iter c+1 issues into stage c&1's partner safely
    }

    const int grow = lane >> 2;
    const int gcol = (lane & 3) * 2;

    if (mode == 0) {
#pragma unroll
        for (int nn = 0; nn < 4; nn++) {
            int col = n0 + wn * 32 + nn * 8 + gcol;
            float2 bv = *(const float2*)&bias[col];
#pragma unroll
            for (int t = 0; t < 4; t++) {
                int row0 = m0 + wm * 64 + t * 16 + grow;
                float2 o0 = {acc[t][nn][0] + bv.x, acc[t][nn][1] + bv.y};
                float2 o1 = {acc[t][nn][2] + bv.x, acc[t][nn][3] + bv.y};
                *(float2*)&C[(size_t)row0 * N + col] = o0;
                *(float2*)&C[(size_t)(row0 + 8) * N + col] = o1;
            }
        }
    } else {
        // scatter to [B][H][S][64]; q split hi/lo pre-scaled 0.125, k/v plain
        const int colb = n0 + wn * 32;
        const int t3 = colb >> 10;               // 0=q 1=k 2=v (warp-uniform)
        const int hh = (colb & 1023) >> 6;
        const int bidx = m0 >> 11;
#pragma unroll
        for (int nn = 0; nn < 4; nn++) {
            int col = colb + nn * 8 + gcol;
            int d = col & 63;
            float2 bv = *(const float2*)&bias[col];
#pragma unroll
            for (int t = 0; t < 4; t++) {
                int row0 = m0 + wm * 64 + t * 16 + grow;
                int s = row0 & 2047;
                size_t base  = ((size_t)(bidx * Hn + hh) * Sn + s) * 64 + d;
                size_t base8 = base + 8 * 64;
                float vx = acc[t][nn][0] + bv.x, vy = acc[t][nn][1] + bv.y;
                float wx = acc[t][nn][2] + bv.x, wy = acc[t][nn][3] + bv.y;
                if (t3 == 0) {
                    vx *= 0.125f; vy *= 0.125f; wx *= 0.125f; wy *= 0.125f;
                    *(uint32_t*)&qh[base]  = pack_f16(vx, vy);
                    *(uint32_t*)&ql[base]  = pack_f16(vx - f16_val(vx), vy - f16_val(vy));
                    *(uint32_t*)&qh[base8] = pack_f16(wx, wy);
                    *(uint32_t*)&ql[base8] = pack_f16(wx - f16_val(wx), wy - f16_val(wy));
                } else if (t3 == 1) {
                    *(uint32_t*)&kk[base]  = pack_f16(vx, vy);
                    *(uint32_t*)&kk[base8] = pack_f16(wx, wy);
                } else {
                    *(uint32_t*)&vv[base]  = pack_f16(vx, vy);
                    *(uint32_t*)&vv[base8] = pack_f16(wx, wy);
                }
            }
        }
    }
}

// ---------------------------------------------------------------------------
// Tensor-core flash attention, fp16 2-split (Q/P split, K/V plain).
// CTA = 128 q rows of one (b,h); 8 warps x 16 rows; 64-key tiles, 2-stage cp.async.
// smem: Q hi/lo 32KB + 2 stages x (K 8KB + V 8KB) = 64KB.
// ---------------------------------------------------------------------------
#define ASMEM 65536

__global__ __launch_bounds__(256, 2) void attn_mma_kernel(
    const __half* __restrict__ Qh, const __half* __restrict__ Ql,
    const __half* __restrict__ Kp, const __half* __restrict__ Vp,
    __half* __restrict__ out_hi, __half* __restrict__ out_lo)
{
    extern __shared__ char sma[];
    const uint32_t sb  = smem_u32(sma);
    const uint32_t sQh = sb, sQl = sb + 16384;
    const int tid = threadIdx.x, wid = tid >> 5, lane = tid & 31;
    const int qt = (gridDim.x - 1) - blockIdx.x;    // heavy tiles first
    const int h = blockIdx.y, b = blockIdx.z;
    const int q0 = qt * 128;
    const size_t head = ((size_t)(b * Hn + h)) * Sn * 64;

    // load Q tile (hi+lo) once: group 0
    for (int i = tid; i < 1024; i += 256) {
        int row = i >> 3, c = i & 7;
        uint32_t d = SWZ(row, c);
        const size_t g = head + (size_t)(q0 + row) * 64 + c * 8;
        CP16(sQh + d, Qh + g);
        CP16(sQl + d, Ql + g);
    }
    CP_COMMIT();

    auto issue_kv = [&](int kt) {
        uint32_t st = sb + 32768 + (uint32_t)(kt & 1) * 16384;
        const int k0 = kt * 64;
        for (int i = tid; i < 512; i += 256) {
            int row = i >> 3, c = i & 7;
            uint32_t d = SWZ(row, c);
            size_t g = head + (size_t)(k0 + row) * 64 + c * 8;
            CP16(st + d,        Kp + g);
            CP16(st + 8192 + d, Vp + g);
        }
        CP_COMMIT();
    };

    const int nkt = 2 * qt + 2;
    issue_kv(0);
    CP_WAIT1();          // Q (group 0) complete
    __syncthreads();

    // per-lane fragment geometry
    const int qr      = wid * 16 + (lane & 15);
    const int qc_add  = (lane >> 4);
    const int kr_base = ((lane >> 4) << 3) + (lane & 7);
    const int kc_add  = ((lane >> 3) & 1);
    const int vr      = (lane & 15);

    // hoist Q-hi fragments to registers (Q-lo reloaded per ks: reused 4x)
    uint32_t qhr[4][4];
#pragma unroll
    for (int ks = 0; ks < 4; ks++)
        ldsm_x4(qhr[ks], sQh + SWZ(qr, 2 * ks + qc_add));

    float oacc[8][4];
#pragma unroll
    for (int j = 0; j < 8; j++)
#pragma unroll
        for (int q = 0; q < 4; q++) oacc[j][q] = 0.f;
    float m[2] = {-1e30f, -1e30f}, l[2] = {0.f, 0.f};

    for (int c = 0; c < nkt; c++) {
        CP_WAIT0();
        __syncthreads();
        if (c + 1 < nkt) issue_kv(c + 1);   // overlaps with compute

        const uint32_t stK = sb + 32768 + (uint32_t)(c & 1) * 16384;
        const uint32_t stV = stK + 8192;
        const int k0 = c * 64;

        // ---- S = Q K^T (Q split, K plain: 2 MMAs per acc frag) ----
        float sacc[8][4];
#pragma unroll
        for (int j = 0; j < 8; j++)
#pragma unroll
            for (int q = 0; q < 4; q++) sacc[j][q] = 0.f;

#pragma unroll
        for (int ks = 0; ks < 4; ks++) {
            uint32_t qlr[4];
            ldsm_x4(qlr, sQl + SWZ(qr, 2 * ks + qc_add));
#pragma unroll
            for (int kg = 0; kg < 4; kg++) {
                uint32_t kh4[4];
                ldsm_x4(kh4, stK + SWZ(kg * 16 + kr_base, 2 * ks + kc_add));
                mma_f16(sacc[2*kg],   qhr[ks], kh4[0], kh4[1]);
                mma_f16(sacc[2*kg],   qlr,     kh4[0], kh4[1]);
                mma_f16(sacc[2*kg+1], qhr[ks], kh4[2], kh4[3]);
                mma_f16(sacc[2*kg+1], qlr,     kh4[2], kh4[3]);
            }
        }

        // ---- causal mask ----
        const int r0g = q0 + wid * 16 + (lane >> 2);
        if (k0 + 63 > q0 + wid * 16) {
#pragma unroll
            for (int j = 0; j < 8; j++) {
                int key = k0 + 8 * j + (lane & 3) * 2;
                if (key     > r0g)     sacc[j][0] = -1e30f;
                if (key + 1 > r0g)     sacc[j][1] = -1e30f;
                if (key     > r0g + 8) sacc[j][2] = -1e30f;
                if (key + 1 > r0g + 8) sacc[j][3] = -1e30f;
            }
        }

        // ---- online softmax per row-group ----
#pragma unroll
        for (int rg = 0; rg < 2; rg++) {
            float tm = -1e30f;
#pragma unroll
            for (int j = 0; j < 8; j++)
                tm = fmaxf(tm, fmaxf(sacc[j][2*rg], sacc[j][2*rg+1]));
            tm = fmaxf(tm, __shfl_xor_sync(0xffffffffu, tm, 1));
            tm = fmaxf(tm, __shfl_xor_sync(0xffffffffu, tm, 2));
            float mnew = fmaxf(m[rg], tm);
            float corr = __expf(m[rg] - mnew);
            m[rg] = mnew;
            float rs = 0.f;
#pragma unroll
            for (int j = 0; j < 8; j++) {
                float e0 = __expf(sacc[j][2*rg]   - mnew);
                float e1 = __expf(sacc[j][2*rg+1] - mnew);
                sacc[j][2*rg] = e0; sacc[j][2*rg+1] = e1;
                rs += e0 + e1;
            }
            rs += __shfl_xor_sync(0xffffffffu, rs, 1);
            rs += __shfl_xor_sync(0xffffffffu, rs, 2);
            l[rg] = l[rg] * corr + rs;
#pragma unroll
            for (int j = 0; j < 8; j++) {
                oacc[j][2*rg]   *= corr;
                oacc[j][2*rg+1] *= corr;
            }
        }

        // ---- O += P V (P split in-register, V plain) ----
#pragma unroll
        for (int t = 0; t < 4; t++) {
            uint32_t phi[4], plo[4];
#pragma unroll
            for (int half = 0; half < 2; half++) {
                const float p0 = sacc[2*t + half][0], p1 = sacc[2*t + half][1];
                const float p2 = sacc[2*t + half][2], p3 = sacc[2*t + half][3];
                phi[2*half]     = pack_f16(p0, p1);
                phi[2*half + 1] = pack_f16(p2, p3);
                plo[2*half]     = pack_f16(p0 - f16_val(p0), p1 - f16_val(p1));
                plo[2*half + 1] = pack_f16(p2 - f16_val(p2), p3 - f16_val(p3));
            }
            int vrow = t * 16 + vr;
#pragma unroll
            for (int p = 0; p < 4; p++) {
                uint32_t vh4[4];
                ldsm_x4_t(vh4, stV + SWZ(vrow, 2 * p + qc_add));
                mma_f16(oacc[2*p],   phi, vh4[0], vh4[1]);
                mma_f16(oacc[2*p],   plo, vh4[0], vh4[1]);
                mma_f16(oacc[2*p+1], phi, vh4[2], vh4[3]);
                mma_f16(oacc[2*p+1], plo, vh4[2], vh4[3]);
            }
        }
        __syncthreads();   // all warps done reading stage c before next overwrite cycle
    }

    // ---- normalize + fp16 hi/lo split store to [row=(b,s)][h*64+d] ----
    const float inv0 = 1.f / l[0], inv1 = 1.f / l[1];
    const int s0 = q0 + wid * 16 + (lane >> 2);
#pragma unroll
    for (int j = 0; j < 8; j++) {
        int dcol = h * 64 + 8 * j + (lane & 3) * 2;
        size_t i0 = (size_t)(b * Sn + s0) * HHD + dcol;
        size_t i1 = i0 + (size_t)8 * HHD;
        float vx = oacc[j][0] * inv0, vy = oacc[j][1] * inv0;
        *(uint32_t*)&out_hi[i0] = pack_f16(vx, vy);
        *(uint32_t*)&out_lo[i0] = pack_f16(vx - f16_val(vx), vy - f16_val(vy));
        float v2 = oacc[j][2] * inv1, v3 = oacc[j][3] * inv1;
        *(uint32_t*)&out_hi[i1] = pack_f16(v2, v3);
        *(uint32_t*)&out_lo[i1] = pack_f16(v2 - f16_val(v2), v3 - f16_val(v3));
    }
}

// ---------------------------------------------------------------------------
extern "C" void kernel_launch(void* const* d_in, const int* in_sizes, int n_in,
                              void* d_out, int out_size)
{
    const float* x      = (const float*)d_in[0];
    const float* w_qkv  = (const float*)d_in[1];
    const float* b_qkv  = (const float*)d_in[2];
    const float* w_proj = (const float*)d_in[3];
    const float* b_proj = (const float*)d_in[4];
    float* out = (float*)d_out;

    __half *xhi, *xlo, *wq, *wp, *ath, *atl, *qh, *ql, *kk, *vv;
    cudaGetSymbolAddress((void**)&xhi, g_xhi);
    cudaGetSymbolAddress((void**)&xlo, g_xlo);
    cudaGetSymbolAddress((void**)&wq, g_wqkv);
    cudaGetSymbolAddress((void**)&wp, g_wproj);
    cudaGetSymbolAddress((void**)&ath, g_att_hi);
    cudaGetSymbolAddress((void**)&atl, g_att_lo);
    cudaGetSymbolAddress((void**)&qh, g_q_hi);
    cudaGetSymbolAddress((void**)&ql, g_q_lo);
    cudaGetSymbolAddress((void**)&kk, g_k);
    cudaGetSymbolAddress((void**)&vv, g_v);

    cudaFuncSetAttribute(gemm_f16s_kernel,
                         cudaFuncAttributeMaxDynamicSharedMemorySize, SMEM_G);
    cudaFuncSetAttribute(attn_mma_kernel,
                         cudaFuncAttributeMaxDynamicSharedMemorySize, ASMEM);

    // prep: x -> fp16 hi/lo split; weights -> plain fp16
    split_f16_kernel<<<(Mrows * Dn) / 4 / 256, 256>>>(x, xhi, xlo);
    tof16_kernel<<<(Dn * QKVROW) / 4 / 256, 256>>>(w_qkv, wq);
    tof16_kernel<<<(HHD * Dn) / 4 / 256, 256>>>(w_proj, wp);

    // 1) QKV GEMM -> head-major q(split, 0.125x)/k/v fp16
    gemm_f16s_kernel<<<dim3(QKVROW / BN, Mrows / BM), 256, SMEM_G>>>(
        xhi, xlo, wq, b_qkv, nullptr, qh, ql, kk, vv, Mrows, QKVROW, Dn, 1);

    // 2) tensor-core causal flash attention -> att fp16 hi/lo
    attn_mma_kernel<<<dim3(Sn / 128, Hn, Bn), 256, ASMEM>>>(
        qh, ql, kk, vv, ath, atl);

    // 3) proj GEMM -> fp32 out + bias
    gemm_f16s_kernel<<<dim3(Dn / BN, Mrows / BM), 256, SMEM_G>>>(
        ath, atl, wp, b_proj, out, nullptr, nullptr, nullptr, nullptr,
        Mrows, Dn, HHD, 0);
}

// round 6
// speedup vs baseline: 3.7259x; 1.0024x over previous
#include <cuda_runtime.h>
#include <cuda_fp16.h>
#include <math.h>
#include <stdint.h>

// Problem constants
#define Bn   4
#define Sn   2048
#define Dn   1024
#define Hn   16
#define HDn  64
#define HHD  (Hn*HDn)      // 1024
#define QKVROW (3*HHD)     // 3072
#define Mrows (Bn*Sn)      // 8192

// ---------------- scratch (allocation-free device globals) ----------------
__device__ __align__(128) __half g_xhi[(size_t)Mrows * Dn];
__device__ __align__(128) __half g_xlo[(size_t)Mrows * Dn];
__device__ __align__(128) __half g_wqkv[(size_t)Dn * QKVROW];   // [K][N] plain fp16
__device__ __align__(128) __half g_wproj[(size_t)HHD * Dn];     // [K][N] plain fp16
// Q/K/V head-major [B][H][S][64]; Q split hi/lo (pre-scaled 0.125), K/V plain
__device__ __align__(128) __half g_q_hi[(size_t)Bn * Hn * Sn * HDn];
__device__ __align__(128) __half g_q_lo[(size_t)Bn * Hn * Sn * HDn];
__device__ __align__(128) __half g_k[(size_t)Bn * Hn * Sn * HDn];
__device__ __align__(128) __half g_v[(size_t)Bn * Hn * Sn * HDn];
__device__ __align__(128) __half g_att_hi[(size_t)Mrows * HHD];
__device__ __align__(128) __half g_att_lo[(size_t)Mrows * HHD];

// ---------------- PTX helpers ----------------
__device__ __forceinline__ uint32_t smem_u32(const void* p) {
    uint32_t a;
    asm("{ .reg .u64 t; cvta.to.shared.u64 t, %1; cvt.u32.u64 %0, t; }" : "=r"(a) : "l"(p));
    return a;
}
#define CP16(s, g) asm volatile("cp.async.cg.shared.global [%0], [%1], 16;" :: "r"(s), "l"(g))
#define CP_COMMIT() asm volatile("cp.async.commit_group;" ::: "memory")
#define CP_WAITG(n) asm volatile("cp.async.wait_group %0;" :: "n"(n) : "memory")

__device__ __forceinline__ void ldsm_x4(uint32_t (&r)[4], uint32_t addr) {
    asm volatile("ldmatrix.sync.aligned.m8n8.x4.shared.b16 {%0,%1,%2,%3}, [%4];"
                 : "=r"(r[0]), "=r"(r[1]), "=r"(r[2]), "=r"(r[3]) : "r"(addr));
}
__device__ __forceinline__ void ldsm_x4_t(uint32_t (&r)[4], uint32_t addr) {
    asm volatile("ldmatrix.sync.aligned.m8n8.x4.trans.shared.b16 {%0,%1,%2,%3}, [%4];"
                 : "=r"(r[0]), "=r"(r[1]), "=r"(r[2]), "=r"(r[3]) : "r"(addr));
}
__device__ __forceinline__ void mma_f16(float (&c)[4], const uint32_t (&a)[4],
                                        uint32_t b0, uint32_t b1) {
    asm volatile(
        "mma.sync.aligned.m16n8k16.row.col.f32.f16.f16.f32 "
        "{%0,%1,%2,%3}, {%4,%5,%6,%7}, {%8,%9}, {%0,%1,%2,%3};"
        : "+f"(c[0]), "+f"(c[1]), "+f"(c[2]), "+f"(c[3])
        : "r"(a[0]), "r"(a[1]), "r"(a[2]), "r"(a[3]), "r"(b0), "r"(b1));
}
__device__ __forceinline__ uint32_t pack_f16(float lo, float hi) {
    uint32_t r;
    asm("cvt.rn.f16x2.f32 %0, %1, %2;" : "=r"(r) : "f"(hi), "f"(lo));
    return r;
}
__device__ __forceinline__ float f16_val(float x) {
    return __half2float(__float2half(x));
}
// XOR-swizzled smem offset: 128B rows, 16B chunks, conflict-free ldmatrix
#define SWZ(row, c) ((uint32_t)((row) * 128 + (((c) ^ ((row) & 7)) << 4)))

// ---------------- prep kernels ----------------
__global__ __launch_bounds__(256) void split_f16_kernel(
    const float* __restrict__ in, __half* __restrict__ hi, __half* __restrict__ lo)
{
    int i = blockIdx.x * 256 + threadIdx.x;
    float4 v = ((const float4*)in)[i];
    ((uint32_t*)hi)[i * 2 + 0] = pack_f16(v.x, v.y);
    ((uint32_t*)hi)[i * 2 + 1] = pack_f16(v.z, v.w);
    ((uint32_t*)lo)[i * 2 + 0] = pack_f16(v.x - f16_val(v.x), v.y - f16_val(v.y));
    ((uint32_t*)lo)[i * 2 + 1] = pack_f16(v.z - f16_val(v.z), v.w - f16_val(v.w));
}
__global__ __launch_bounds__(256) void tof16_kernel(
    const float* __restrict__ in, __half* __restrict__ out)
{
    int i = blockIdx.x * 256 + threadIdx.x;
    float4 v = ((const float4*)in)[i];
    ((uint32_t*)out)[i * 2 + 0] = pack_f16(v.x, v.y);
    ((uint32_t*)out)[i * 2 + 1] = pack_f16(v.z, v.w);
}

// ---------------- fp16 A-split 2-MMA tensor-core GEMM, 3-stage pipeline ----------------
#define BM 128
#define BN 128
#define BKc 32
#define LDA 40
#define LDB 136
#define A_BYTES (BM * LDA * 2)          // 10240
#define B_BYTES (BKc * LDB * 2)         // 8704
#define STAGE   (2 * A_BYTES + B_BYTES) // 29184
#define GSTAGES 3
#define SMEM_G  (GSTAGES * STAGE)       // 87552

__global__ __launch_bounds__(256, 2) void gemm_f16s_kernel(
    const __half* __restrict__ Ahi, const __half* __restrict__ Alo,
    const __half* __restrict__ Bw,
    const float* __restrict__ bias, float* __restrict__ C,
    __half* __restrict__ qh, __half* __restrict__ ql,
    __half* __restrict__ kk, __half* __restrict__ vv,
    int M, int N, int K, int mode)
{
    extern __shared__ char smg[];
    const uint32_t sb = smem_u32(smg);
    const int tid  = threadIdx.x;
    const int wid  = tid >> 5;
    const int lane = tid & 31;
    const int wm   = wid & 1;
    const int wn   = wid >> 1;
    const int n0   = blockIdx.x * BN;
    const int m0   = blockIdx.y * BM;
    const int NC   = K / BKc;

    const int a_row = tid >> 2, a_c = tid & 3;
    const int b_row = tid >> 4, b_c = tid & 15;

    auto issue = [&](int c) {
        const uint32_t sa = sb + (uint32_t)(c % GSTAGES) * STAGE;
        const int k0 = c * BKc;
#pragma unroll
        for (int r = 0; r < 2; r++) {
            int row = a_row + r * 64;
            uint32_t d = sa + (uint32_t)row * (LDA * 2) + (uint32_t)a_c * 16;
            const __half* s = Ahi + (size_t)(m0 + row) * K + k0 + a_c * 8;
            CP16(d, s);
            CP16(d + A_BYTES, s + (Alo - Ahi));
        }
#pragma unroll
        for (int r = 0; r < 2; r++) {
            int row = b_row + r * 16;
            uint32_t d = sa + 2 * A_BYTES + (uint32_t)row * (LDB * 2) + (uint32_t)b_c * 16;
            CP16(d, Bw + (size_t)(k0 + row) * N + n0 + b_c * 8);
        }
        CP_COMMIT();
    };

    float acc[4][4][4];
#pragma unroll
    for (int i = 0; i < 4; i++)
#pragma unroll
        for (int j = 0; j < 4; j++)
#pragma unroll
            for (int q = 0; q < 4; q++) acc[i][j][q] = 0.f;

    const int a_base = (wm * 64 + (lane & 15)) * LDA + ((lane >> 4) << 3);
    const int b_base = (lane & 15) * LDB + wn * 32 + ((lane >> 4) << 3);

    issue(0);
    issue(1);
    for (int c = 0; c < NC; c++) {
        CP_WAITG(1);          // stage c landed (2-chunk prefetch distance)
        __syncthreads();      // also guards reuse of stage (c+2)%3 (read in iter c-1)
        if (c + 2 < NC) issue(c + 2); else CP_COMMIT();

        const uint32_t sa  = sb + (uint32_t)(c % GSTAGES) * STAGE;
        const uint32_t sal = sa + A_BYTES;
        const uint32_t sbw = sa + 2 * A_BYTES;

#pragma unroll
        for (int step = 0; step < 2; step++) {
            uint32_t ah[4][4], al[4][4];
            uint32_t bw[4][2];
#pragma unroll
            for (int t = 0; t < 4; t++) {
                uint32_t off = (uint32_t)(a_base + t * 16 * LDA + step * 16) * 2;
                ldsm_x4(ah[t], sa + off);
                ldsm_x4(al[t], sal + off);
            }
#pragma unroll
            for (int p = 0; p < 2; p++) {
                uint32_t off = (uint32_t)(b_base + step * 16 * LDB + p * 16) * 2;
                uint32_t r[4];
                ldsm_x4_t(r, sbw + off);
                bw[2*p][0]   = r[0]; bw[2*p][1]   = r[1];
                bw[2*p+1][0] = r[2]; bw[2*p+1][1] = r[3];
            }
#pragma unroll
            for (int t = 0; t < 4; t++)
#pragma unroll
                for (int nn = 0; nn < 4; nn++) {
                    mma_f16(acc[t][nn], ah[t], bw[nn][0], bw[nn][1]);
                    mma_f16(acc[t][nn], al[t], bw[nn][0], bw[nn][1]);
                }
        }
    }

    const int grow = lane >> 2;
    const int gcol = (lane & 3) * 2;

    if (mode == 0) {
#pragma unroll
        for (int nn = 0; nn < 4; nn++) {
            int col = n0 + wn * 32 + nn * 8 + gcol;
            float2 bv = *(const float2*)&bias[col];
#pragma unroll
            for (int t = 0; t < 4; t++) {
                int row0 = m0 + wm * 64 + t * 16 + grow;
                float2 o0 = {acc[t][nn][0] + bv.x, acc[t][nn][1] + bv.y};
                float2 o1 = {acc[t][nn][2] + bv.x, acc[t][nn][3] + bv.y};
                *(float2*)&C[(size_t)row0 * N + col] = o0;
                *(float2*)&C[(size_t)(row0 + 8) * N + col] = o1;
            }
        }
    } else {
        const int colb = n0 + wn * 32;
        const int t3 = colb >> 10;               // 0=q 1=k 2=v (warp-uniform)
        const int hh = (colb & 1023) >> 6;
        const int bidx = m0 >> 11;
#pragma unroll
        for (int nn = 0; nn < 4; nn++) {
            int col = colb + nn * 8 + gcol;
            int d = col & 63;
            float2 bv = *(const float2*)&bias[col];
#pragma unroll
            for (int t = 0; t < 4; t++) {
                int row0 = m0 + wm * 64 + t * 16 + grow;
                int s = row0 & 2047;
                size_t base  = ((size_t)(bidx * Hn + hh) * Sn + s) * 64 + d;
                size_t base8 = base + 8 * 64;
                float vx = acc[t][nn][0] + bv.x, vy = acc[t][nn][1] + bv.y;
                float wx = acc[t][nn][2] + bv.x, wy = acc[t][nn][3] + bv.y;
                if (t3 == 0) {
                    vx *= 0.125f; vy *= 0.125f; wx *= 0.125f; wy *= 0.125f;
                    *(uint32_t*)&qh[base]  = pack_f16(vx, vy);
                    *(uint32_t*)&ql[base]  = pack_f16(vx - f16_val(vx), vy - f16_val(vy));
                    *(uint32_t*)&qh[base8] = pack_f16(wx, wy);
                    *(uint32_t*)&ql[base8] = pack_f16(wx - f16_val(wx), wy - f16_val(wy));
                } else if (t3 == 1) {
                    *(uint32_t*)&kk[base]  = pack_f16(vx, vy);
                    *(uint32_t*)&kk[base8] = pack_f16(wx, wy);
                } else {
                    *(uint32_t*)&vv[base]  = pack_f16(vx, vy);
                    *(uint32_t*)&vv[base8] = pack_f16(wx, wy);
                }
            }
        }
    }
}

// ---------------------------------------------------------------------------
// Tensor-core flash attention, fp16 2-split, 4-stage KV pipeline.
// CTA = 128 q rows of one (b,h); 8 warps x 16 rows; 64-key tiles.
// smem: Q hi/lo 32KB + 4 stages x (K 8KB + V 8KB) = 96KB.
// ---------------------------------------------------------------------------
#define KVSTAGES 4
#define ASMEM (32768 + KVSTAGES * 16384)   // 98304

__global__ __launch_bounds__(256, 2) void attn_mma_kernel(
    const __half* __restrict__ Qh, const __half* __restrict__ Ql,
    const __half* __restrict__ Kp, const __half* __restrict__ Vp,
    __half* __restrict__ out_hi, __half* __restrict__ out_lo)
{
    extern __shared__ char sma[];
    const uint32_t sb  = smem_u32(sma);
    const uint32_t sQh = sb, sQl = sb + 16384;
    const int tid = threadIdx.x, wid = tid >> 5, lane = tid & 31;
    const int qt = (gridDim.x - 1) - blockIdx.x;    // heavy tiles first
    const int h = blockIdx.y, b = blockIdx.z;
    const int q0 = qt * 128;
    const size_t head = ((size_t)(b * Hn + h)) * Sn * 64;

    // Q tile (hi+lo): group 0
    for (int i = tid; i < 1024; i += 256) {
        int row = i >> 3, c = i & 7;
        uint32_t d = SWZ(row, c);
        const size_t g = head + (size_t)(q0 + row) * 64 + c * 8;
        CP16(sQh + d, Qh + g);
        CP16(sQl + d, Ql + g);
    }
    CP_COMMIT();

    auto issue_kv = [&](int kt) {
        uint32_t st = sb + 32768 + (uint32_t)(kt & (KVSTAGES - 1)) * 16384;
        const int k0 = kt * 64;
        for (int i = tid; i < 512; i += 256) {
            int row = i >> 3, c = i & 7;
            uint32_t d = SWZ(row, c);
            size_t g = head + (size_t)(k0 + row) * 64 + c * 8;
            CP16(st + d,        Kp + g);
            CP16(st + 8192 + d, Vp + g);
        }
        CP_COMMIT();
    };

    const int nkt = 2 * qt + 2;
    // prologue: always 3 kv groups (dummy commits keep group-count invariant)
#pragma unroll
    for (int kt = 0; kt < 3; kt++) {
        if (kt < nkt) issue_kv(kt); else CP_COMMIT();
    }
    CP_WAITG(3);          // Q (group 0) complete
    __syncthreads();

    // per-lane fragment geometry
    const int qr      = wid * 16 + (lane & 15);
    const int qc_add  = (lane >> 4);
    const int kr_base = ((lane >> 4) << 3) + (lane & 7);
    const int kc_add  = ((lane >> 3) & 1);
    const int vr      = (lane & 15);

    // hoist Q-hi fragments to registers
    uint32_t qhr[4][4];
#pragma unroll
    for (int ks = 0; ks < 4; ks++)
        ldsm_x4(qhr[ks], sQh + SWZ(qr, 2 * ks + qc_add));

    float oacc[8][4];
#pragma unroll
    for (int j = 0; j < 8; j++)
#pragma unroll
        for (int q = 0; q < 4; q++) oacc[j][q] = 0.f;
    float m[2] = {-1e30f, -1e30f}, l[2] = {0.f, 0.f};

    for (int c = 0; c < nkt; c++) {
        CP_WAITG(2);       // kv stage c landed (3-tile prefetch distance)
        __syncthreads();   // also guards reuse of stage (c+3)&3 (read in iter c-1)
        if (c + 3 < nkt) issue_kv(c + 3); else CP_COMMIT();

        const uint32_t stK = sb + 32768 + (uint32_t)(c & (KVSTAGES - 1)) * 16384;
        const uint32_t stV = stK + 8192;
        const int k0 = c * 64;

        // ---- S = Q K^T ----
        float sacc[8][4];
#pragma unroll
        for (int j = 0; j < 8; j++)
#pragma unroll
            for (int q = 0; q < 4; q++) sacc[j][q] = 0.f;

#pragma unroll
        for (int ks = 0; ks < 4; ks++) {
            uint32_t qlr[4];
            ldsm_x4(qlr, sQl + SWZ(qr, 2 * ks + qc_add));
#pragma unroll
            for (int kg = 0; kg < 4; kg++) {
                uint32_t kh4[4];
                ldsm_x4(kh4, stK + SWZ(kg * 16 + kr_base, 2 * ks + kc_add));
                mma_f16(sacc[2*kg],   qhr[ks], kh4[0], kh4[1]);
                mma_f16(sacc[2*kg],   qlr,     kh4[0], kh4[1]);
                mma_f16(sacc[2*kg+1], qhr[ks], kh4[2], kh4[3]);
                mma_f16(sacc[2*kg+1], qlr,     kh4[2], kh4[3]);
            }
        }

        // ---- causal mask ----
        const int r0g = q0 + wid * 16 + (lane >> 2);
        if (k0 + 63 > q0 + wid * 16) {
#pragma unroll
            for (int j = 0; j < 8; j++) {
                int key = k0 + 8 * j + (lane & 3) * 2;
                if (key     > r0g)     sacc[j][0] = -1e30f;
                if (key + 1 > r0g)     sacc[j][1] = -1e30f;
                if (key     > r0g + 8) sacc[j][2] = -1e30f;
                if (key + 1 > r0g + 8) sacc[j][3] = -1e30f;
            }
        }

        // ---- online softmax per row-group ----
#pragma unroll
        for (int rg = 0; rg < 2; rg++) {
            float tm = -1e30f;
#pragma unroll
            for (int j = 0; j < 8; j++)
                tm = fmaxf(tm, fmaxf(sacc[j][2*rg], sacc[j][2*rg+1]));
            tm = fmaxf(tm, __shfl_xor_sync(0xffffffffu, tm, 1));
            tm = fmaxf(tm, __shfl_xor_sync(0xffffffffu, tm, 2));
            float mnew = fmaxf(m[rg], tm);
            float corr = __expf(m[rg] - mnew);
            m[rg] = mnew;
            float rs = 0.f;
#pragma unroll
            for (int j = 0; j < 8; j++) {
                float e0 = __expf(sacc[j][2*rg]   - mnew);
                float e1 = __expf(sacc[j][2*rg+1] - mnew);
                sacc[j][2*rg] = e0; sacc[j][2*rg+1] = e1;
                rs += e0 + e1;
            }
            rs += __shfl_xor_sync(0xffffffffu, rs, 1);
            rs += __shfl_xor_sync(0xffffffffu, rs, 2);
            l[rg] = l[rg] * corr + rs;
#pragma unroll
            for (int j = 0; j < 8; j++) {
                oacc[j][2*rg]   *= corr;
                oacc[j][2*rg+1] *= corr;
            }
        }

        // ---- O += P V (P split in-register, V plain) ----
#pragma unroll
        for (int t = 0; t < 4; t++) {
            uint32_t phi[4], plo[4];
#pragma unroll
            for (int half = 0; half < 2; half++) {
                const float p0 = sacc[2*t + half][0], p1 = sacc[2*t + half][1];
                const float p2 = sacc[2*t + half][2], p3 = sacc[2*t + half][3];
                phi[2*half]     = pack_f16(p0, p1);
                phi[2*half + 1] = pack_f16(p2, p3);
                plo[2*half]     = pack_f16(p0 - f16_val(p0), p1 - f16_val(p1));
                plo[2*half + 1] = pack_f16(p2 - f16_val(p2), p3 - f16_val(p3));
            }
            int vrow = t * 16 + vr;
#pragma unroll
            for (int p = 0; p < 4; p++) {
                uint32_t vh4[4];
                ldsm_x4_t(vh4, stV + SWZ(vrow, 2 * p + qc_add));
                mma_f16(oacc[2*p],   phi, vh4[0], vh4[1]);
                mma_f16(oacc[2*p],   plo, vh4[0], vh4[1]);
                mma_f16(oacc[2*p+1], phi, vh4[2], vh4[3]);
                mma_f16(oacc[2*p+1], plo, vh4[2], vh4[3]);
            }
        }
    }

    // ---- normalize + fp16 hi/lo split store ----
    const float inv0 = 1.f / l[0], inv1 = 1.f / l[1];
    const int s0 = q0 + wid * 16 + (lane >> 2);
#pragma unroll
    for (int j = 0; j < 8; j++) {
        int dcol = h * 64 + 8 * j + (lane & 3) * 2;
        size_t i0 = (size_t)(b * Sn + s0) * HHD + dcol;
        size_t i1 = i0 + (size_t)8 * HHD;
        float vx = oacc[j][0] * inv0, vy = oacc[j][1] * inv0;
        *(uint32_t*)&out_hi[i0] = pack_f16(vx, vy);
        *(uint32_t*)&out_lo[i0] = pack_f16(vx - f16_val(vx), vy - f16_val(vy));
        float v2 = oacc[j][2] * inv1, v3 = oacc[j][3] * inv1;
        *(uint32_t*)&out_hi[i1] = pack_f16(v2, v3);
        *(uint32_t*)&out_lo[i1] = pack_f16(v2 - f16_val(v2), v3 - f16_val(v3));
    }
}

// ---------------------------------------------------------------------------
extern "C" void kernel_launch(void* const* d_in, const int* in_sizes, int n_in,
                              void* d_out, int out_size)
{
    const float* x      = (const float*)d_in[0];
    const float* w_qkv  = (const float*)d_in[1];
    const float* b_qkv  = (const float*)d_in[2];
    const float* w_proj = (const float*)d_in[3];
    const float* b_proj = (const float*)d_in[4];
    float* out = (float*)d_out;

    __half *xhi, *xlo, *wq, *wp, *ath, *atl, *qh, *ql, *kk, *vv;
    cudaGetSymbolAddress((void**)&xhi, g_xhi);
    cudaGetSymbolAddress((void**)&xlo, g_xlo);
    cudaGetSymbolAddress((void**)&wq, g_wqkv);
    cudaGetSymbolAddress((void**)&wp, g_wproj);
    cudaGetSymbolAddress((void**)&ath, g_att_hi);
    cudaGetSymbolAddress((void**)&atl, g_att_lo);
    cudaGetSymbolAddress((void**)&qh, g_q_hi);
    cudaGetSymbolAddress((void**)&ql, g_q_lo);
    cudaGetSymbolAddress((void**)&kk, g_k);
    cudaGetSymbolAddress((void**)&vv, g_v);

    cudaFuncSetAttribute(gemm_f16s_kernel,
                         cudaFuncAttributeMaxDynamicSharedMemorySize, SMEM_G);
    cudaFuncSetAttribute(attn_mma_kernel,
                         cudaFuncAttributeMaxDynamicSharedMemorySize, ASMEM);

    // prep
    split_f16_kernel<<<(Mrows * Dn) / 4 / 256, 256>>>(x, xhi, xlo);
    tof16_kernel<<<(Dn * QKVROW) / 4 / 256, 256>>>(w_qkv, wq);
    tof16_kernel<<<(HHD * Dn) / 4 / 256, 256>>>(w_proj, wp);

    // 1) QKV GEMM -> head-major q(split, 0.125x)/k/v fp16
    gemm_f16s_kernel<<<dim3(QKVROW / BN, Mrows / BM), 256, SMEM_G>>>(
        xhi, xlo, wq, b_qkv, nullptr, qh, ql, kk, vv, Mrows, QKVROW, Dn, 1);

    // 2) tensor-core causal flash attention -> att fp16 hi/lo
    attn_mma_kernel<<<dim3(Sn / 128, Hn, Bn), 256, ASMEM>>>(
        qh, ql, kk, vv, ath, atl);

    // 3) proj GEMM -> fp32 out + bias
    gemm_f16s_kernel<<<dim3(Dn / BN, Mrows / BM), 256, SMEM_G>>>(
        ath, atl, wp, b_proj, out, nullptr, nullptr, nullptr, nullptr,
        Mrows, Dn, HHD, 0);
}

// round 7
// speedup vs baseline: 4.7316x; 1.2699x over previous
#include <cuda_runtime.h>
#include <cuda_fp16.h>
#include <math.h>
#include <stdint.h>

// Problem constants
#define Bn   4
#define Sn   2048
#define Dn   1024
#define Hn   16
#define HDn  64
#define HHD  (Hn*HDn)      // 1024
#define QKVROW (3*HHD)     // 3072
#define Mrows (Bn*Sn)      // 8192

// ---------------- scratch (allocation-free device globals) ----------------
__device__ __align__(128) __half g_xhi[(size_t)Mrows * Dn];
__device__ __align__(128) __half g_xlo[(size_t)Mrows * Dn];
__device__ __align__(128) __half g_wqkv[(size_t)Dn * QKVROW];   // [K][N] plain fp16
__device__ __align__(128) __half g_wproj[(size_t)HHD * Dn];     // [K][N] plain fp16
// Q/K/V head-major [B][H][S][64]; Q split hi/lo (pre-scaled 0.125), K/V plain
__device__ __align__(128) __half g_q_hi[(size_t)Bn * Hn * Sn * HDn];
__device__ __align__(128) __half g_q_lo[(size_t)Bn * Hn * Sn * HDn];
__device__ __align__(128) __half g_k[(size_t)Bn * Hn * Sn * HDn];
__device__ __align__(128) __half g_v[(size_t)Bn * Hn * Sn * HDn];
__device__ __align__(128) __half g_att_hi[(size_t)Mrows * HHD];
__device__ __align__(128) __half g_att_lo[(size_t)Mrows * HHD];

// ---------------- PTX helpers ----------------
__device__ __forceinline__ uint32_t smem_u32(const void* p) {
    uint32_t a;
    asm("{ .reg .u64 t; cvta.to.shared.u64 t, %1; cvt.u32.u64 %0, t; }" : "=r"(a) : "l"(p));
    return a;
}
#define CP16(s, g) asm volatile("cp.async.cg.shared.global [%0], [%1], 16;" :: "r"(s), "l"(g))
#define CP_COMMIT() asm volatile("cp.async.commit_group;" ::: "memory")
#define CP_WAITG(n) asm volatile("cp.async.wait_group %0;" :: "n"(n) : "memory")

__device__ __forceinline__ void ldsm_x4(uint32_t (&r)[4], uint32_t addr) {
    asm volatile("ldmatrix.sync.aligned.m8n8.x4.shared.b16 {%0,%1,%2,%3}, [%4];"
                 : "=r"(r[0]), "=r"(r[1]), "=r"(r[2]), "=r"(r[3]) : "r"(addr));
}
__device__ __forceinline__ void ldsm_x4_t(uint32_t (&r)[4], uint32_t addr) {
    asm volatile("ldmatrix.sync.aligned.m8n8.x4.trans.shared.b16 {%0,%1,%2,%3}, [%4];"
                 : "=r"(r[0]), "=r"(r[1]), "=r"(r[2]), "=r"(r[3]) : "r"(addr));
}
__device__ __forceinline__ void mma_f16(float (&c)[4], const uint32_t (&a)[4],
                                        uint32_t b0, uint32_t b1) {
    asm volatile(
        "mma.sync.aligned.m16n8k16.row.col.f32.f16.f16.f32 "
        "{%0,%1,%2,%3}, {%4,%5,%6,%7}, {%8,%9}, {%0,%1,%2,%3};"
        : "+f"(c[0]), "+f"(c[1]), "+f"(c[2]), "+f"(c[3])
        : "r"(a[0]), "r"(a[1]), "r"(a[2]), "r"(a[3]), "r"(b0), "r"(b1));
}
__device__ __forceinline__ uint32_t pack_f16(float lo, float hi) {
    uint32_t r;
    asm("cvt.rn.f16x2.f32 %0, %1, %2;" : "=r"(r) : "f"(hi), "f"(lo));
    return r;
}
__device__ __forceinline__ float f16_val(float x) {
    return __half2float(__float2half(x));
}
// XOR-swizzled smem offset for 128B rows (byte offset); c = 16B chunk 0..7
#define SWZ(row, c) ((uint32_t)((row) * 128 + (((c) ^ ((row) & 7)) << 4)))
// 256B-row B tile: per-128B-half XOR swizzle; ncol = fp16 column 0..127
__device__ __forceinline__ uint32_t bswz(int row, int ncol) {
    int ch = ncol >> 3;            // 16B chunk 0..15
    return (uint32_t)(row * 256 + ((ch >> 3) << 7) + (((ch & 7) ^ (row & 7)) << 4));
}

// ---------------- prep kernels ----------------
__global__ __launch_bounds__(256) void split_f16_kernel(
    const float* __restrict__ in, __half* __restrict__ hi, __half* __restrict__ lo)
{
    int i = blockIdx.x * 256 + threadIdx.x;
    float4 v = ((const float4*)in)[i];
    ((uint32_t*)hi)[i * 2 + 0] = pack_f16(v.x, v.y);
    ((uint32_t*)hi)[i * 2 + 1] = pack_f16(v.z, v.w);
    ((uint32_t*)lo)[i * 2 + 0] = pack_f16(v.x - f16_val(v.x), v.y - f16_val(v.y));
    ((uint32_t*)lo)[i * 2 + 1] = pack_f16(v.z - f16_val(v.z), v.w - f16_val(v.w));
}
__global__ __launch_bounds__(256) void tof16_kernel(
    const float* __restrict__ in, __half* __restrict__ out)
{
    int i = blockIdx.x * 256 + threadIdx.x;
    float4 v = ((const float4*)in)[i];
    ((uint32_t*)out)[i * 2 + 0] = pack_f16(v.x, v.y);
    ((uint32_t*)out)[i * 2 + 1] = pack_f16(v.z, v.w);
}

// ---------------- fp16 A-split 2-MMA tensor-core GEMM, BK=64, 2 stages -------
#define BM 128
#define BN 128
#define BKc 64
#define A_BYTES (BM * 128)              // 16384 per split buffer (128B rows)
#define B_BYTES (BKc * 256)             // 16384 (256B rows)
#define STAGE   (2 * A_BYTES + B_BYTES) // 49152
#define SMEM_G  (2 * STAGE)             // 98304

__global__ __launch_bounds__(256, 2) void gemm_f16s_kernel(
    const __half* __restrict__ Ahi, const __half* __restrict__ Alo,
    const __half* __restrict__ Bw,
    const float* __restrict__ bias, float* __restrict__ C,
    __half* __restrict__ qh, __half* __restrict__ ql,
    __half* __restrict__ kk, __half* __restrict__ vv,
    int M, int N, int K, int mode)
{
    extern __shared__ char smg[];
    const uint32_t sb = smem_u32(smg);
    const int tid  = threadIdx.x;
    const int wid  = tid >> 5;
    const int lane = tid & 31;
    const int wm   = wid & 1;
    const int wn   = wid >> 1;
    const int n0   = blockIdx.x * BN;
    const int m0   = blockIdx.y * BM;
    const int NC   = K / BKc;           // 16

    auto issue = [&](int c) {
        const uint32_t sa = sb + (uint32_t)(c & 1) * STAGE;
        const int k0 = c * BKc;
#pragma unroll
        for (int r = 0; r < 4; r++) {            // A hi+lo: 1024 chunks each
            int idx = tid + r * 256;
            int row = idx >> 3, ch = idx & 7;
            uint32_t d = sa + SWZ(row, ch);
            const __half* s = Ahi + (size_t)(m0 + row) * K + k0 + ch * 8;
            CP16(d, s);
            CP16(d + A_BYTES, s + (Alo - Ahi));
        }
#pragma unroll
        for (int r = 0; r < 4; r++) {            // B: 1024 chunks
            int idx = tid + r * 256;
            int row = idx >> 4, ch = idx & 15;
            uint32_t d = sa + 2 * A_BYTES + bswz(row, ch * 8);
            CP16(d, Bw + (size_t)(k0 + row) * N + n0 + ch * 8);
        }
        CP_COMMIT();
    };

    float acc[4][4][4];
#pragma unroll
    for (int i = 0; i < 4; i++)
#pragma unroll
        for (int j = 0; j < 4; j++)
#pragma unroll
            for (int q = 0; q < 4; q++) acc[i][j][q] = 0.f;

    issue(0);
    for (int c = 0; c < NC; c++) {
        CP_WAITG(0);
        __syncthreads();          // all warps' copies visible; stage c^1 free for reuse
        if (c + 1 < NC) issue(c + 1);

        const uint32_t sa  = sb + (uint32_t)(c & 1) * STAGE;
        const uint32_t sal = sa + A_BYTES;
        const uint32_t sbw = sa + 2 * A_BYTES;

#pragma unroll
        for (int s = 0; s < 4; s++) {             // 4 k16-steps per chunk
            uint32_t ah[4][4], al[4][4];
            uint32_t bw[4][2];
#pragma unroll
            for (int t = 0; t < 4; t++) {
                int row = wm * 64 + t * 16 + (lane & 15);
                uint32_t off = SWZ(row, 2 * s + (lane >> 4));
                ldsm_x4(ah[t], sa + off);
                ldsm_x4(al[t], sal + off);
            }
#pragma unroll
            for (int p = 0; p < 2; p++) {
                int row  = s * 16 + (lane & 15);
                int ncol = wn * 32 + p * 16 + ((lane >> 4) << 3);
                uint32_t r[4];
                ldsm_x4_t(r, sbw + bswz(row, ncol));
                bw[2*p][0]   = r[0]; bw[2*p][1]   = r[1];
                bw[2*p+1][0] = r[2]; bw[2*p+1][1] = r[3];
            }
#pragma unroll
            for (int t = 0; t < 4; t++)
#pragma unroll
                for (int nn = 0; nn < 4; nn++) {
                    mma_f16(acc[t][nn], ah[t], bw[nn][0], bw[nn][1]);
                    mma_f16(acc[t][nn], al[t], bw[nn][0], bw[nn][1]);
                }
        }
    }

    const int grow = lane >> 2;
    const int gcol = (lane & 3) * 2;

    if (mode == 0) {
#pragma unroll
        for (int nn = 0; nn < 4; nn++) {
            int col = n0 + wn * 32 + nn * 8 + gcol;
            float2 bv = *(const float2*)&bias[col];
#pragma unroll
            for (int t = 0; t < 4; t++) {
                int row0 = m0 + wm * 64 + t * 16 + grow;
                float2 o0 = {acc[t][nn][0] + bv.x, acc[t][nn][1] + bv.y};
                float2 o1 = {acc[t][nn][2] + bv.x, acc[t][nn][3] + bv.y};
                *(float2*)&C[(size_t)row0 * N + col] = o0;
                *(float2*)&C[(size_t)(row0 + 8) * N + col] = o1;
            }
        }
    } else {
        const int colb = n0 + wn * 32;
        const int t3 = colb >> 10;               // 0=q 1=k 2=v (warp-uniform)
        const int hh = (colb & 1023) >> 6;
        const int bidx = m0 >> 11;
#pragma unroll
        for (int nn = 0; nn < 4; nn++) {
            int col = colb + nn * 8 + gcol;
            int d = col & 63;
            float2 bv = *(const float2*)&bias[col];
#pragma unroll
            for (int t = 0; t < 4; t++) {
                int row0 = m0 + wm * 64 + t * 16 + grow;
                int s = row0 & 2047;
                size_t base  = ((size_t)(bidx * Hn + hh) * Sn + s) * 64 + d;
                size_t base8 = base + 8 * 64;
                float vx = acc[t][nn][0] + bv.x, vy = acc[t][nn][1] + bv.y;
                float wx = acc[t][nn][2] + bv.x, wy = acc[t][nn][3] + bv.y;
                if (t3 == 0) {
                    vx *= 0.125f; vy *= 0.125f; wx *= 0.125f; wy *= 0.125f;
                    *(uint32_t*)&qh[base]  = pack_f16(vx, vy);
                    *(uint32_t*)&ql[base]  = pack_f16(vx - f16_val(vx), vy - f16_val(vy));
                    *(uint32_t*)&qh[base8] = pack_f16(wx, wy);
                    *(uint32_t*)&ql[base8] = pack_f16(wx - f16_val(wx), wy - f16_val(wy));
                } else if (t3 == 1) {
                    *(uint32_t*)&kk[base]  = pack_f16(vx, vy);
                    *(uint32_t*)&kk[base8] = pack_f16(wx, wy);
                } else {
                    *(uint32_t*)&vv[base]  = pack_f16(vx, vy);
                    *(uint32_t*)&vv[base8] = pack_f16(wx, wy);
                }
            }
        }
    }
}

// ---------------------------------------------------------------------------
// Tensor-core flash attention, fp16 (Q split for QK^T, P plain for PV).
// CTA = 128 q rows of one (b,h); 8 warps x 16 rows; 64-key tiles, 4-stage KV.
// smem: Q hi/lo 32KB + 4 stages x (K 8KB + V 8KB) = 96KB.
// ---------------------------------------------------------------------------
#define KVSTAGES 4
#define ASMEM (32768 + KVSTAGES * 16384)   // 98304

__global__ __launch_bounds__(256, 2) void attn_mma_kernel(
    const __half* __restrict__ Qh, const __half* __restrict__ Ql,
    const __half* __restrict__ Kp, const __half* __restrict__ Vp,
    __half* __restrict__ out_hi, __half* __restrict__ out_lo)
{
    extern __shared__ char sma[];
    const uint32_t sb  = smem_u32(sma);
    const uint32_t sQh = sb, sQl = sb + 16384;
    const int tid = threadIdx.x, wid = tid >> 5, lane = tid & 31;
    const int qt = (gridDim.x - 1) - blockIdx.x;    // heavy tiles first
    const int h = blockIdx.y, b = blockIdx.z;
    const int q0 = qt * 128;
    const size_t head = ((size_t)(b * Hn + h)) * Sn * 64;

    // Q tile (hi+lo): group 0
    for (int i = tid; i < 1024; i += 256) {
        int row = i >> 3, c = i & 7;
        uint32_t d = SWZ(row, c);
        const size_t g = head + (size_t)(q0 + row) * 64 + c * 8;
        CP16(sQh + d, Qh + g);
        CP16(sQl + d, Ql + g);
    }
    CP_COMMIT();

    auto issue_kv = [&](int kt) {
        uint32_t st = sb + 32768 + (uint32_t)(kt & (KVSTAGES - 1)) * 16384;
        const int k0 = kt * 64;
        for (int i = tid; i < 512; i += 256) {
            int row = i >> 3, c = i & 7;
            uint32_t d = SWZ(row, c);
            size_t g = head + (size_t)(k0 + row) * 64 + c * 8;
            CP16(st + d,        Kp + g);
            CP16(st + 8192 + d, Vp + g);
        }
        CP_COMMIT();
    };

    const int nkt = 2 * qt + 2;
#pragma unroll
    for (int kt = 0; kt < 3; kt++) {
        if (kt < nkt) issue_kv(kt); else CP_COMMIT();
    }
    CP_WAITG(3);          // Q (group 0) complete
    __syncthreads();

    const int qr      = wid * 16 + (lane & 15);
    const int qc_add  = (lane >> 4);
    const int kr_base = ((lane >> 4) << 3) + (lane & 7);
    const int kc_add  = ((lane >> 3) & 1);
    const int vr      = (lane & 15);

    // hoist Q-hi fragments to registers
    uint32_t qhr[4][4];
#pragma unroll
    for (int ks = 0; ks < 4; ks++)
        ldsm_x4(qhr[ks], sQh + SWZ(qr, 2 * ks + qc_add));

    float oacc[8][4];
#pragma unroll
    for (int j = 0; j < 8; j++)
#pragma unroll
        for (int q = 0; q < 4; q++) oacc[j][q] = 0.f;
    float m[2] = {-1e30f, -1e30f}, l[2] = {0.f, 0.f};

    for (int c = 0; c < nkt; c++) {
        CP_WAITG(2);
        __syncthreads();
        if (c + 3 < nkt) issue_kv(c + 3); else CP_COMMIT();

        const uint32_t stK = sb + 32768 + (uint32_t)(c & (KVSTAGES - 1)) * 16384;
        const uint32_t stV = stK + 8192;
        const int k0 = c * 64;

        // ---- S = Q K^T (Q split, K plain) ----
        float sacc[8][4];
#pragma unroll
        for (int j = 0; j < 8; j++)
#pragma unroll
            for (int q = 0; q < 4; q++) sacc[j][q] = 0.f;

#pragma unroll
        for (int ks = 0; ks < 4; ks++) {
            uint32_t qlr[4];
            ldsm_x4(qlr, sQl + SWZ(qr, 2 * ks + qc_add));
#pragma unroll
            for (int kg = 0; kg < 4; kg++) {
                uint32_t kh4[4];
                ldsm_x4(kh4, stK + SWZ(kg * 16 + kr_base, 2 * ks + kc_add));
                mma_f16(sacc[2*kg],   qhr[ks], kh4[0], kh4[1]);
                mma_f16(sacc[2*kg],   qlr,     kh4[0], kh4[1]);
                mma_f16(sacc[2*kg+1], qhr[ks], kh4[2], kh4[3]);
                mma_f16(sacc[2*kg+1], qlr,     kh4[2], kh4[3]);
            }
        }

        // ---- causal mask ----
        const int r0g = q0 + wid * 16 + (lane >> 2);
        if (k0 + 63 > q0 + wid * 16) {
#pragma unroll
            for (int j = 0; j < 8; j++) {
                int key = k0 + 8 * j + (lane & 3) * 2;
                if (key     > r0g)     sacc[j][0] = -1e30f;
                if (key + 1 > r0g)     sacc[j][1] = -1e30f;
                if (key     > r0g + 8) sacc[j][2] = -1e30f;
                if (key + 1 > r0g + 8) sacc[j][3] = -1e30f;
            }
        }

        // ---- online softmax per row-group ----
#pragma unroll
        for (int rg = 0; rg < 2; rg++) {
            float tm = -1e30f;
#pragma unroll
            for (int j = 0; j < 8; j++)
                tm = fmaxf(tm, fmaxf(sacc[j][2*rg], sacc[j][2*rg+1]));
            tm = fmaxf(tm, __shfl_xor_sync(0xffffffffu, tm, 1));
            tm = fmaxf(tm, __shfl_xor_sync(0xffffffffu, tm, 2));
            float mnew = fmaxf(m[rg], tm);
            float corr = __expf(m[rg] - mnew);
            m[rg] = mnew;
            float rs = 0.f;
#pragma unroll
            for (int j = 0; j < 8; j++) {
                float e0 = __expf(sacc[j][2*rg]   - mnew);
                float e1 = __expf(sacc[j][2*rg+1] - mnew);
                sacc[j][2*rg] = e0; sacc[j][2*rg+1] = e1;
                rs += e0 + e1;
            }
            rs += __shfl_xor_sync(0xffffffffu, rs, 1);
            rs += __shfl_xor_sync(0xffffffffu, rs, 2);
            l[rg] = l[rg] * corr + rs;
#pragma unroll
            for (int j = 0; j < 8; j++) {
                oacc[j][2*rg]   *= corr;
                oacc[j][2*rg+1] *= corr;
            }
        }

        // ---- O += P V (P plain fp16: 1 MMA per frag) ----
#pragma unroll
        for (int t = 0; t < 4; t++) {
            uint32_t phi[4];
            phi[0] = pack_f16(sacc[2*t][0],   sacc[2*t][1]);
            phi[1] = pack_f16(sacc[2*t][2],   sacc[2*t][3]);
            phi[2] = pack_f16(sacc[2*t+1][0], sacc[2*t+1][1]);
            phi[3] = pack_f16(sacc[2*t+1][2], sacc[2*t+1][3]);
            int vrow = t * 16 + vr;
#pragma unroll
            for (int p = 0; p < 4; p++) {
                uint32_t vh4[4];
                ldsm_x4_t(vh4, stV + SWZ(vrow, 2 * p + qc_add));
                mma_f16(oacc[2*p],   phi, vh4[0], vh4[1]);
                mma_f16(oacc[2*p+1], phi, vh4[2], vh4[3]);
            }
        }
    }

    // ---- normalize + fp16 hi/lo split store ----
    const float inv0 = 1.f / l[0], inv1 = 1.f / l[1];
    const int s0 = q0 + wid * 16 + (lane >> 2);
#pragma unroll
    for (int j = 0; j < 8; j++) {
        int dcol = h * 64 + 8 * j + (lane & 3) * 2;
        size_t i0 = (size_t)(b * Sn + s0) * HHD + dcol;
        size_t i1 = i0 + (size_t)8 * HHD;
        float vx = oacc[j][0] * inv0, vy = oacc[j][1] * inv0;
        *(uint32_t*)&out_hi[i0] = pack_f16(vx, vy);
        *(uint32_t*)&out_lo[i0] = pack_f16(vx - f16_val(vx), vy - f16_val(vy));
        float v2 = oacc[j][2] * inv1, v3 = oacc[j][3] * inv1;
        *(uint32_t*)&out_hi[i1] = pack_f16(v2, v3);
        *(uint32_t*)&out_lo[i1] = pack_f16(v2 - f16_val(v2), v3 - f16_val(v3));
    }
}

// ---------------------------------------------------------------------------
extern "C" void kernel_launch(void* const* d_in, const int* in_sizes, int n_in,
                              void* d_out, int out_size)
{
    const float* x      = (const float*)d_in[0];
    const float* w_qkv  = (const float*)d_in[1];
    const float* b_qkv  = (const float*)d_in[2];
    const float* w_proj = (const float*)d_in[3];
    const float* b_proj = (const float*)d_in[4];
    float* out = (float*)d_out;

    __half *xhi, *xlo, *wq, *wp, *ath, *atl, *qh, *ql, *kk, *vv;
    cudaGetSymbolAddress((void**)&xhi, g_xhi);
    cudaGetSymbolAddress((void**)&xlo, g_xlo);
    cudaGetSymbolAddress((void**)&wq, g_wqkv);
    cudaGetSymbolAddress((void**)&wp, g_wproj);
    cudaGetSymbolAddress((void**)&ath, g_att_hi);
    cudaGetSymbolAddress((void**)&atl, g_att_lo);
    cudaGetSymbolAddress((void**)&qh, g_q_hi);
    cudaGetSymbolAddress((void**)&ql, g_q_lo);
    cudaGetSymbolAddress((void**)&kk, g_k);
    cudaGetSymbolAddress((void**)&vv, g_v);

    cudaFuncSetAttribute(gemm_f16s_kernel,
                         cudaFuncAttributeMaxDynamicSharedMemorySize, SMEM_G);
    cudaFuncSetAttribute(attn_mma_kernel,
                         cudaFuncAttributeMaxDynamicSharedMemorySize, ASMEM);

    // prep
    split_f16_kernel<<<(Mrows * Dn) / 4 / 256, 256>>>(x, xhi, xlo);
    tof16_kernel<<<(Dn * QKVROW) / 4 / 256, 256>>>(w_qkv, wq);
    tof16_kernel<<<(HHD * Dn) / 4 / 256, 256>>>(w_proj, wp);

    // 1) QKV GEMM -> head-major q(split, 0.125x)/k/v fp16
    gemm_f16s_kernel<<<dim3(QKVROW / BN, Mrows / BM), 256, SMEM_G>>>(
        xhi, xlo, wq, b_qkv, nullptr, qh, ql, kk, vv, Mrows, QKVROW, Dn, 1);

    // 2) tensor-core causal flash attention -> att fp16 hi/lo
    attn_mma_kernel<<<dim3(Sn / 128, Hn, Bn), 256, ASMEM>>>(
        qh, ql, kk, vv, ath, atl);

    // 3) proj GEMM -> fp32 out + bias
    gemm_f16s_kernel<<<dim3(Dn / BN, Mrows / BM), 256, SMEM_G>>>(
        ath, atl, wp, b_proj, out, nullptr, nullptr, nullptr, nullptr,
        Mrows, Dn, HHD, 0);
}

// round 8
// speedup vs baseline: 5.2602x; 1.1117x over previous
#include <cuda_runtime.h>
#include <cuda_fp16.h>
#include <math.h>
#include <stdint.h>

// Problem constants
#define Bn   4
#define Sn   2048
#define Dn   1024
#define Hn   16
#define HDn  64
#define HHD  (Hn*HDn)      // 1024
#define QKVROW (3*HHD)     // 3072
#define Mrows (Bn*Sn)      // 8192

// Q pre-scale: rsqrt(64) * log2(e)  (softmax done in exp2 domain)
#define QSCALE 0.1803368801111f

// ---------------- scratch (allocation-free device globals) ----------------
__device__ __align__(128) __half g_xhi[(size_t)Mrows * Dn];
__device__ __align__(128) __half g_xlo[(size_t)Mrows * Dn];
__device__ __align__(128) __half g_wqkv[(size_t)Dn * QKVROW];   // [K][N] fp16
__device__ __align__(128) __half g_wproj[(size_t)HHD * Dn];     // [K][N] fp16
// Q/K/V head-major [B][H][S][64]; all plain fp16 (Q pre-scaled by QSCALE)
__device__ __align__(128) __half g_q[(size_t)Bn * Hn * Sn * HDn];
__device__ __align__(128) __half g_k[(size_t)Bn * Hn * Sn * HDn];
__device__ __align__(128) __half g_v[(size_t)Bn * Hn * Sn * HDn];
__device__ __align__(128) __half g_att_hi[(size_t)Mrows * HHD];
__device__ __align__(128) __half g_att_lo[(size_t)Mrows * HHD];

// ---------------- PTX helpers ----------------
__device__ __forceinline__ uint32_t smem_u32(const void* p) {
    uint32_t a;
    asm("{ .reg .u64 t; cvta.to.shared.u64 t, %1; cvt.u32.u64 %0, t; }" : "=r"(a) : "l"(p));
    return a;
}
#define CP16(s, g) asm volatile("cp.async.cg.shared.global [%0], [%1], 16;" :: "r"(s), "l"(g))
#define CP_COMMIT() asm volatile("cp.async.commit_group;" ::: "memory")
#define CP_WAITG(n) asm volatile("cp.async.wait_group %0;" :: "n"(n) : "memory")

__device__ __forceinline__ void ldsm_x4(uint32_t (&r)[4], uint32_t addr) {
    asm volatile("ldmatrix.sync.aligned.m8n8.x4.shared.b16 {%0,%1,%2,%3}, [%4];"
                 : "=r"(r[0]), "=r"(r[1]), "=r"(r[2]), "=r"(r[3]) : "r"(addr));
}
__device__ __forceinline__ void ldsm_x4_t(uint32_t (&r)[4], uint32_t addr) {
    asm volatile("ldmatrix.sync.aligned.m8n8.x4.trans.shared.b16 {%0,%1,%2,%3}, [%4];"
                 : "=r"(r[0]), "=r"(r[1]), "=r"(r[2]), "=r"(r[3]) : "r"(addr));
}
__device__ __forceinline__ void mma_f16(float (&c)[4], const uint32_t (&a)[4],
                                        uint32_t b0, uint32_t b1) {
    asm volatile(
        "mma.sync.aligned.m16n8k16.row.col.f32.f16.f16.f32 "
        "{%0,%1,%2,%3}, {%4,%5,%6,%7}, {%8,%9}, {%0,%1,%2,%3};"
        : "+f"(c[0]), "+f"(c[1]), "+f"(c[2]), "+f"(c[3])
        : "r"(a[0]), "r"(a[1]), "r"(a[2]), "r"(a[3]), "r"(b0), "r"(b1));
}
__device__ __forceinline__ uint32_t pack_f16(float lo, float hi) {
    uint32_t r;
    asm("cvt.rn.f16x2.f32 %0, %1, %2;" : "=r"(r) : "f"(hi), "f"(lo));
    return r;
}
__device__ __forceinline__ float f16_val(float x) {
    return __half2float(__float2half(x));
}
__device__ __forceinline__ float ex2(float x) {
    float r;
    asm("ex2.approx.ftz.f32 %0, %1;" : "=f"(r) : "f"(x));
    return r;
}
// XOR-swizzled smem offset for 128B rows (byte offset); c = 16B chunk 0..7
#define SWZ(row, c) ((uint32_t)((row) * 128 + (((c) ^ ((row) & 7)) << 4)))
// 256B-row B tile: per-128B-half XOR swizzle; ncol = fp16 column 0..127
__device__ __forceinline__ uint32_t bswz(int row, int ncol) {
    int ch = ncol >> 3;
    return (uint32_t)(row * 256 + ((ch >> 3) << 7) + (((ch & 7) ^ (row & 7)) << 4));
}

// ---------------- fused prep kernel ----------------
#define NX4  ((Mrows * Dn) / 4)          // 2097152
#define NW14 ((Dn * QKVROW) / 4)         // 786432
#define NW24 ((HHD * Dn) / 4)            // 262144

__global__ __launch_bounds__(256) void prep_kernel(
    const float* __restrict__ x, const float* __restrict__ wq_in,
    const float* __restrict__ wp_in,
    __half* __restrict__ xhi, __half* __restrict__ xlo,
    __half* __restrict__ wq, __half* __restrict__ wp)
{
    int i = blockIdx.x * 256 + threadIdx.x;
    if (i < NX4) {
        float4 v = ((const float4*)x)[i];
        ((uint32_t*)xhi)[i * 2 + 0] = pack_f16(v.x, v.y);
        ((uint32_t*)xhi)[i * 2 + 1] = pack_f16(v.z, v.w);
        ((uint32_t*)xlo)[i * 2 + 0] = pack_f16(v.x - f16_val(v.x), v.y - f16_val(v.y));
        ((uint32_t*)xlo)[i * 2 + 1] = pack_f16(v.z - f16_val(v.z), v.w - f16_val(v.w));
    } else if (i < NX4 + NW14) {
        int j = i - NX4;
        float4 v = ((const float4*)wq_in)[j];
        ((uint32_t*)wq)[j * 2 + 0] = pack_f16(v.x, v.y);
        ((uint32_t*)wq)[j * 2 + 1] = pack_f16(v.z, v.w);
    } else {
        int j = i - NX4 - NW14;
        float4 v = ((const float4*)wp_in)[j];
        ((uint32_t*)wp)[j * 2 + 0] = pack_f16(v.x, v.y);
        ((uint32_t*)wp)[j * 2 + 1] = pack_f16(v.z, v.w);
    }
}

// ---------------- fp16 A-split 2-MMA tensor-core GEMM, BK=64, 2 stages -------
#define BM 128
#define BN 128
#define BKc 64
#define A_BYTES (BM * 128)              // 16384 per split buffer
#define B_BYTES (BKc * 256)             // 16384
#define STAGE   (2 * A_BYTES + B_BYTES) // 49152
#define SMEM_G  (2 * STAGE)             // 98304

__global__ __launch_bounds__(256, 2) void gemm_f16s_kernel(
    const __half* __restrict__ Ahi, const __half* __restrict__ Alo,
    const __half* __restrict__ Bw,
    const float* __restrict__ bias, float* __restrict__ C,
    __half* __restrict__ qq, __half* __restrict__ kk, __half* __restrict__ vv,
    int M, int N, int K, int mode)
{
    extern __shared__ char smg[];
    const uint32_t sb = smem_u32(smg);
    const int tid  = threadIdx.x;
    const int wid  = tid >> 5;
    const int lane = tid & 31;
    const int wm   = wid & 1;
    const int wn   = wid >> 1;
    const int n0   = blockIdx.x * BN;
    const int m0   = blockIdx.y * BM;
    const int NC   = K / BKc;

    auto issue = [&](int c) {
        const uint32_t sa = sb + (uint32_t)(c & 1) * STAGE;
        const int k0 = c * BKc;
#pragma unroll
        for (int r = 0; r < 4; r++) {
            int idx = tid + r * 256;
            int row = idx >> 3, ch = idx & 7;
            uint32_t d = sa + SWZ(row, ch);
            const __half* s = Ahi + (size_t)(m0 + row) * K + k0 + ch * 8;
            CP16(d, s);
            CP16(d + A_BYTES, s + (Alo - Ahi));
        }
#pragma unroll
        for (int r = 0; r < 4; r++) {
            int idx = tid + r * 256;
            int row = idx >> 4, ch = idx & 15;
            uint32_t d = sa + 2 * A_BYTES + bswz(row, ch * 8);
            CP16(d, Bw + (size_t)(k0 + row) * N + n0 + ch * 8);
        }
        CP_COMMIT();
    };

    float acc[4][4][4];
#pragma unroll
    for (int i = 0; i < 4; i++)
#pragma unroll
        for (int j = 0; j < 4; j++)
#pragma unroll
            for (int q = 0; q < 4; q++) acc[i][j][q] = 0.f;

    issue(0);
    for (int c = 0; c < NC; c++) {
        CP_WAITG(0);
        __syncthreads();
        if (c + 1 < NC) issue(c + 1);

        const uint32_t sa  = sb + (uint32_t)(c & 1) * STAGE;
        const uint32_t sal = sa + A_BYTES;
        const uint32_t sbw = sa + 2 * A_BYTES;

#pragma unroll
        for (int s = 0; s < 4; s++) {
            uint32_t ah[4][4], al[4][4];
            uint32_t bw[4][2];
#pragma unroll
            for (int t = 0; t < 4; t++) {
                int row = wm * 64 + t * 16 + (lane & 15);
                uint32_t off = SWZ(row, 2 * s + (lane >> 4));
                ldsm_x4(ah[t], sa + off);
                ldsm_x4(al[t], sal + off);
            }
#pragma unroll
            for (int p = 0; p < 2; p++) {
                int row  = s * 16 + (lane & 15);
                int ncol = wn * 32 + p * 16 + ((lane >> 4) << 3);
                uint32_t r[4];
                ldsm_x4_t(r, sbw + bswz(row, ncol));
                bw[2*p][0]   = r[0]; bw[2*p][1]   = r[1];
                bw[2*p+1][0] = r[2]; bw[2*p+1][1] = r[3];
            }
#pragma unroll
            for (int t = 0; t < 4; t++)
#pragma unroll
                for (int nn = 0; nn < 4; nn++) {
                    mma_f16(acc[t][nn], ah[t], bw[nn][0], bw[nn][1]);
                    mma_f16(acc[t][nn], al[t], bw[nn][0], bw[nn][1]);
                }
        }
    }

    const int grow = lane >> 2;
    const int gcol = (lane & 3) * 2;

    if (mode == 0) {
#pragma unroll
        for (int nn = 0; nn < 4; nn++) {
            int col = n0 + wn * 32 + nn * 8 + gcol;
            float2 bv = *(const float2*)&bias[col];
#pragma unroll
            for (int t = 0; t < 4; t++) {
                int row0 = m0 + wm * 64 + t * 16 + grow;
                float2 o0 = {acc[t][nn][0] + bv.x, acc[t][nn][1] + bv.y};
                float2 o1 = {acc[t][nn][2] + bv.x, acc[t][nn][3] + bv.y};
                *(float2*)&C[(size_t)row0 * N + col] = o0;
                *(float2*)&C[(size_t)(row0 + 8) * N + col] = o1;
            }
        }
    } else {
        // scatter to [B][H][S][64] plain fp16; q pre-scaled by QSCALE
        const int colb = n0 + wn * 32;
        const int t3 = colb >> 10;               // 0=q 1=k 2=v (warp-uniform)
        const int hh = (colb & 1023) >> 6;
        const int bidx = m0 >> 11;
        __half* dst = (t3 == 0) ? qq : (t3 == 1) ? kk : vv;
        const float sc = (t3 == 0) ? QSCALE : 1.f;
#pragma unroll
        for (int nn = 0; nn < 4; nn++) {
            int col = colb + nn * 8 + gcol;
            int d = col & 63;
            float2 bv = *(const float2*)&bias[col];
#pragma unroll
            for (int t = 0; t < 4; t++) {
                int row0 = m0 + wm * 64 + t * 16 + grow;
                int s = row0 & 2047;
                size_t base  = ((size_t)(bidx * Hn + hh) * Sn + s) * 64 + d;
                size_t base8 = base + 8 * 64;
                float vx = (acc[t][nn][0] + bv.x) * sc, vy = (acc[t][nn][1] + bv.y) * sc;
                float wx = (acc[t][nn][2] + bv.x) * sc, wy = (acc[t][nn][3] + bv.y) * sc;
                *(uint32_t*)&dst[base]  = pack_f16(vx, vy);
                *(uint32_t*)&dst[base8] = pack_f16(wx, wy);
            }
        }
    }
}

// ---------------------------------------------------------------------------
// Tensor-core flash attention, plain fp16 Q/K/V/P, exp2-domain softmax.
// CTA = 128 q rows of one (b,h); 8 warps x 16 rows; 64-key tiles, 4-stage KV.
// smem: Q 16KB + 4 stages x (K 8KB + V 8KB) = 80KB.
// ---------------------------------------------------------------------------
#define KVSTAGES 4
#define ASMEM (16384 + KVSTAGES * 16384)   // 81920

__global__ __launch_bounds__(256, 2) void attn_mma_kernel(
    const __half* __restrict__ Qp,
    const __half* __restrict__ Kp, const __half* __restrict__ Vp,
    __half* __restrict__ out_hi, __half* __restrict__ out_lo)
{
    extern __shared__ char sma[];
    const uint32_t sb = smem_u32(sma);
    const uint32_t sQ = sb;
    const int tid = threadIdx.x, wid = tid >> 5, lane = tid & 31;
    const int qt = (gridDim.x - 1) - blockIdx.x;    // heavy tiles first
    const int h = blockIdx.y, b = blockIdx.z;
    const int q0 = qt * 128;
    const size_t head = ((size_t)(b * Hn + h)) * Sn * 64;

    // Q tile: group 0
    for (int i = tid; i < 1024; i += 256) {
        int row = i >> 3, c = i & 7;
        CP16(sQ + SWZ(row, c), Qp + head + (size_t)(q0 + row) * 64 + c * 8);
    }
    CP_COMMIT();

    auto issue_kv = [&](int kt) {
        uint32_t st = sb + 16384 + (uint32_t)(kt & (KVSTAGES - 1)) * 16384;
        const int k0 = kt * 64;
        for (int i = tid; i < 512; i += 256) {
            int row = i >> 3, c = i & 7;
            uint32_t d = SWZ(row, c);
            size_t g = head + (size_t)(k0 + row) * 64 + c * 8;
            CP16(st + d,        Kp + g);
            CP16(st + 8192 + d, Vp + g);
        }
        CP_COMMIT();
    };

    const int nkt = 2 * qt + 2;
#pragma unroll
    for (int kt = 0; kt < 3; kt++) {
        if (kt < nkt) issue_kv(kt); else CP_COMMIT();
    }
    CP_WAITG(3);          // Q (group 0) complete
    __syncthreads();

    const int qr      = wid * 16 + (lane & 15);
    const int qc_add  = (lane >> 4);
    const int kr_base = ((lane >> 4) << 3) + (lane & 7);
    const int kc_add  = ((lane >> 3) & 1);
    const int vr      = (lane & 15);

    // hoist Q fragments to registers
    uint32_t qhr[4][4];
#pragma unroll
    for (int ks = 0; ks < 4; ks++)
        ldsm_x4(qhr[ks], sQ + SWZ(qr, 2 * ks + qc_add));

    float oacc[8][4];
#pragma unroll
    for (int j = 0; j < 8; j++)
#pragma unroll
        for (int q = 0; q < 4; q++) oacc[j][q] = 0.f;
    float m[2] = {-1e30f, -1e30f}, l[2] = {0.f, 0.f};

    for (int c = 0; c < nkt; c++) {
        CP_WAITG(2);
        __syncthreads();
        if (c + 3 < nkt) issue_kv(c + 3); else CP_COMMIT();

        const uint32_t stK = sb + 16384 + (uint32_t)(c & (KVSTAGES - 1)) * 16384;
        const uint32_t stV = stK + 8192;
        const int k0 = c * 64;

        // ---- S = Q K^T (both plain fp16) ----
        float sacc[8][4];
#pragma unroll
        for (int j = 0; j < 8; j++)
#pragma unroll
            for (int q = 0; q < 4; q++) sacc[j][q] = 0.f;

#pragma unroll
        for (int ks = 0; ks < 4; ks++) {
#pragma unroll
            for (int kg = 0; kg < 4; kg++) {
                uint32_t kh4[4];
                ldsm_x4(kh4, stK + SWZ(kg * 16 + kr_base, 2 * ks + kc_add));
                mma_f16(sacc[2*kg],   qhr[ks], kh4[0], kh4[1]);
                mma_f16(sacc[2*kg+1], qhr[ks], kh4[2], kh4[3]);
            }
        }

        // ---- causal mask ----
        const int r0g = q0 + wid * 16 + (lane >> 2);
        if (k0 + 63 > q0 + wid * 16) {
#pragma unroll
            for (int j = 0; j < 8; j++) {
                int key = k0 + 8 * j + (lane & 3) * 2;
                if (key     > r0g)     sacc[j][0] = -1e30f;
                if (key + 1 > r0g)     sacc[j][1] = -1e30f;
                if (key     > r0g + 8) sacc[j][2] = -1e30f;
                if (key + 1 > r0g + 8) sacc[j][3] = -1e30f;
            }
        }

        // ---- online softmax (exp2 domain) per row-group ----
#pragma unroll
        for (int rg = 0; rg < 2; rg++) {
            float tm = -1e30f;
#pragma unroll
            for (int j = 0; j < 8; j++)
                tm = fmaxf(tm, fmaxf(sacc[j][2*rg], sacc[j][2*rg+1]));
            tm = fmaxf(tm, __shfl_xor_sync(0xffffffffu, tm, 1));
            tm = fmaxf(tm, __shfl_xor_sync(0xffffffffu, tm, 2));
            float mnew = fmaxf(m[rg], tm);
            float corr = ex2(m[rg] - mnew);
            m[rg] = mnew;
            float rs = 0.f;
#pragma unroll
            for (int j = 0; j < 8; j++) {
                float e0 = ex2(sacc[j][2*rg]   - mnew);
                float e1 = ex2(sacc[j][2*rg+1] - mnew);
                sacc[j][2*rg] = e0; sacc[j][2*rg+1] = e1;
                rs += e0 + e1;
            }
            rs += __shfl_xor_sync(0xffffffffu, rs, 1);
            rs += __shfl_xor_sync(0xffffffffu, rs, 2);
            l[rg] = l[rg] * corr + rs;
#pragma unroll
            for (int j = 0; j < 8; j++) {
                oacc[j][2*rg]   *= corr;
                oacc[j][2*rg+1] *= corr;
            }
        }

        // ---- O += P V (P plain fp16) ----
#pragma unroll
        for (int t = 0; t < 4; t++) {
            uint32_t phi[4];
            phi[0] = pack_f16(sacc[2*t][0],   sacc[2*t][1]);
            phi[1] = pack_f16(sacc[2*t][2],   sacc[2*t][3]);
            phi[2] = pack_f16(sacc[2*t+1][0], sacc[2*t+1][1]);
            phi[3] = pack_f16(sacc[2*t+1][2], sacc[2*t+1][3]);
            int vrow = t * 16 + vr;
#pragma unroll
            for (int p = 0; p < 4; p++) {
                uint32_t vh4[4];
                ldsm_x4_t(vh4, stV + SWZ(vrow, 2 * p + qc_add));
                mma_f16(oacc[2*p],   phi, vh4[0], vh4[1]);
                mma_f16(oacc[2*p+1], phi, vh4[2], vh4[3]);
            }
        }
    }

    // ---- normalize + fp16 hi/lo split store ----
    const float inv0 = 1.f / l[0], inv1 = 1.f / l[1];
    const int s0 = q0 + wid * 16 + (lane >> 2);
#pragma unroll
    for (int j = 0; j < 8; j++) {
        int dcol = h * 64 + 8 * j + (lane & 3) * 2;
        size_t i0 = (size_t)(b * Sn + s0) * HHD + dcol;
        size_t i1 = i0 + (size_t)8 * HHD;
        float vx = oacc[j][0] * inv0, vy = oacc[j][1] * inv0;
        *(uint32_t*)&out_hi[i0] = pack_f16(vx, vy);
        *(uint32_t*)&out_lo[i0] = pack_f16(vx - f16_val(vx), vy - f16_val(vy));
        float v2 = oacc[j][2] * inv1, v3 = oacc[j][3] * inv1;
        *(uint32_t*)&out_hi[i1] = pack_f16(v2, v3);
        *(uint32_t*)&out_lo[i1] = pack_f16(v2 - f16_val(v2), v3 - f16_val(v3));
    }
}

// ---------------------------------------------------------------------------
extern "C" void kernel_launch(void* const* d_in, const int* in_sizes, int n_in,
                              void* d_out, int out_size)
{
    const float* x      = (const float*)d_in[0];
    const float* w_qkv  = (const float*)d_in[1];
    const float* b_qkv  = (const float*)d_in[2];
    const float* w_proj = (const float*)d_in[3];
    const float* b_proj = (const float*)d_in[4];
    float* out = (float*)d_out;

    __half *xhi, *xlo, *wq, *wp, *ath, *atl, *qq, *kk, *vv;
    cudaGetSymbolAddress((void**)&xhi, g_xhi);
    cudaGetSymbolAddress((void**)&xlo, g_xlo);
    cudaGetSymbolAddress((void**)&wq, g_wqkv);
    cudaGetSymbolAddress((void**)&wp, g_wproj);
    cudaGetSymbolAddress((void**)&ath, g_att_hi);
    cudaGetSymbolAddress((void**)&atl, g_att_lo);
    cudaGetSymbolAddress((void**)&qq, g_q);
    cudaGetSymbolAddress((void**)&kk, g_k);
    cudaGetSymbolAddress((void**)&vv, g_v);

    cudaFuncSetAttribute(gemm_f16s_kernel,
                         cudaFuncAttributeMaxDynamicSharedMemorySize, SMEM_G);
    cudaFuncSetAttribute(attn_mma_kernel,
                         cudaFuncAttributeMaxDynamicSharedMemorySize, ASMEM);

    // fused prep (x split + both weights)
    prep_kernel<<<(NX4 + NW14 + NW24) / 256, 256>>>(x, w_qkv, w_proj,
                                                    xhi, xlo, wq, wp);

    // 1) QKV GEMM -> head-major q(QSCALE)/k/v plain fp16
    gemm_f16s_kernel<<<dim3(QKVROW / BN, Mrows / BM), 256, SMEM_G>>>(
        xhi, xlo, wq, b_qkv, nullptr, qq, kk, vv, Mrows, QKVROW, Dn, 1);

    // 2) tensor-core causal flash attention -> att fp16 hi/lo
    attn_mma_kernel<<<dim3(Sn / 128, Hn, Bn), 256, ASMEM>>>(
        qq, kk, vv, ath, atl);

    // 3) proj GEMM -> fp32 out + bias
    gemm_f16s_kernel<<<dim3(Dn / BN, Mrows / BM), 256, SMEM_G>>>(
        ath, atl, wp, b_proj, out, nullptr, nullptr, nullptr,
        Mrows, Dn, HHD, 0);
}

// round 9
// speedup vs baseline: 7.4878x; 1.4235x over previous
#include <cuda_runtime.h>
#include <cuda_fp16.h>
#include <math.h>
#include <stdint.h>

// Problem constants
#define Bn   4
#define Sn   2048
#define Dn   1024
#define Hn   16
#define HDn  64
#define HHD  (Hn*HDn)      // 1024
#define QKVROW (3*HHD)     // 3072
#define Mrows (Bn*Sn)      // 8192

// Q pre-scale: rsqrt(64) * log2(e)  (softmax done in exp2 domain)
#define QSCALE 0.1803368801111f

// ---------------- scratch (allocation-free device globals) ----------------
__device__ __align__(128) __half g_x[(size_t)Mrows * Dn];
__device__ __align__(128) __half g_wqkv[(size_t)Dn * QKVROW];   // [K][N] fp16
__device__ __align__(128) __half g_wproj[(size_t)HHD * Dn];     // [K][N] fp16
// Q/K/V head-major [B][H][S][64]; all plain fp16 (Q pre-scaled by QSCALE)
__device__ __align__(128) __half g_q[(size_t)Bn * Hn * Sn * HDn];
__device__ __align__(128) __half g_k[(size_t)Bn * Hn * Sn * HDn];
__device__ __align__(128) __half g_v[(size_t)Bn * Hn * Sn * HDn];
__device__ __align__(128) __half g_att[(size_t)Mrows * HHD];

// ---------------- PTX helpers ----------------
__device__ __forceinline__ uint32_t smem_u32(const void* p) {
    uint32_t a;
    asm("{ .reg .u64 t; cvta.to.shared.u64 t, %1; cvt.u32.u64 %0, t; }" : "=r"(a) : "l"(p));
    return a;
}
#define CP16(s, g) asm volatile("cp.async.cg.shared.global [%0], [%1], 16;" :: "r"(s), "l"(g))
#define CP_COMMIT() asm volatile("cp.async.commit_group;" ::: "memory")
#define CP_WAITG(n) asm volatile("cp.async.wait_group %0;" :: "n"(n) : "memory")

__device__ __forceinline__ void ldsm_x4(uint32_t (&r)[4], uint32_t addr) {
    asm volatile("ldmatrix.sync.aligned.m8n8.x4.shared.b16 {%0,%1,%2,%3}, [%4];"
                 : "=r"(r[0]), "=r"(r[1]), "=r"(r[2]), "=r"(r[3]) : "r"(addr));
}
__device__ __forceinline__ void ldsm_x4_t(uint32_t (&r)[4], uint32_t addr) {
    asm volatile("ldmatrix.sync.aligned.m8n8.x4.trans.shared.b16 {%0,%1,%2,%3}, [%4];"
                 : "=r"(r[0]), "=r"(r[1]), "=r"(r[2]), "=r"(r[3]) : "r"(addr));
}
__device__ __forceinline__ void mma_f16(float (&c)[4], const uint32_t (&a)[4],
                                        uint32_t b0, uint32_t b1) {
    asm volatile(
        "mma.sync.aligned.m16n8k16.row.col.f32.f16.f16.f32 "
        "{%0,%1,%2,%3}, {%4,%5,%6,%7}, {%8,%9}, {%0,%1,%2,%3};"
        : "+f"(c[0]), "+f"(c[1]), "+f"(c[2]), "+f"(c[3])
        : "r"(a[0]), "r"(a[1]), "r"(a[2]), "r"(a[3]), "r"(b0), "r"(b1));
}
__device__ __forceinline__ uint32_t pack_f16(float lo, float hi) {
    uint32_t r;
    asm("cvt.rn.f16x2.f32 %0, %1, %2;" : "=r"(r) : "f"(hi), "f"(lo));
    return r;
}
__device__ __forceinline__ float ex2(float x) {
    float r;
    asm("ex2.approx.ftz.f32 %0, %1;" : "=f"(r) : "f"(x));
    return r;
}
// XOR-swizzled smem offset for 128B rows (byte offset); c = 16B chunk 0..7
#define SWZ(row, c) ((uint32_t)((row) * 128 + (((c) ^ ((row) & 7)) << 4)))
// 256B-row B tile: per-128B-half XOR swizzle; ncol = fp16 column 0..127
__device__ __forceinline__ uint32_t bswz(int row, int ncol) {
    int ch = ncol >> 3;
    return (uint32_t)(row * 256 + ((ch >> 3) << 7) + (((ch & 7) ^ (row & 7)) << 4));
}

// ---------------- fused prep kernel (all plain fp16 conversion) ----------------
#define NX4  ((Mrows * Dn) / 4)          // 2097152
#define NW14 ((Dn * QKVROW) / 4)         // 786432
#define NW24 ((HHD * Dn) / 4)            // 262144

__global__ __launch_bounds__(256) void prep_kernel(
    const float* __restrict__ x, const float* __restrict__ wq_in,
    const float* __restrict__ wp_in,
    __half* __restrict__ xh, __half* __restrict__ wq, __half* __restrict__ wp)
{
    int i = blockIdx.x * 256 + threadIdx.x;
    const float* src;
    __half* dst;
    int j;
    if (i < NX4) {
        src = x; dst = xh; j = i;
    } else if (i < NX4 + NW14) {
        src = wq_in; dst = wq; j = i - NX4;
    } else {
        src = wp_in; dst = wp; j = i - NX4 - NW14;
    }
    float4 v = ((const float4*)src)[j];
    ((uint32_t*)dst)[j * 2 + 0] = pack_f16(v.x, v.y);
    ((uint32_t*)dst)[j * 2 + 1] = pack_f16(v.z, v.w);
}

// ---------------- plain fp16 tensor-core GEMM, BK=64, 2 stages ----------------
#define BM 128
#define BN 128
#define BKc 64
#define A_BYTES (BM * 128)              // 16384 (128B rows)
#define B_BYTES (BKc * 256)             // 16384 (256B rows)
#define STAGE   (A_BYTES + B_BYTES)     // 32768
#define SMEM_G  (2 * STAGE)             // 65536

// mode 0: fp32 out + bias (proj). mode 1: scatter q(QSCALE)/k/v fp16.
__global__ __launch_bounds__(256, 2) void gemm_f16_kernel(
    const __half* __restrict__ Ap, const __half* __restrict__ Bw,
    const float* __restrict__ bias, float* __restrict__ C,
    __half* __restrict__ qq, __half* __restrict__ kk, __half* __restrict__ vv,
    int M, int N, int K, int mode)
{
    extern __shared__ char smg[];
    const uint32_t sb = smem_u32(smg);
    const int tid  = threadIdx.x;
    const int wid  = tid >> 5;
    const int lane = tid & 31;
    const int wm   = wid & 1;
    const int wn   = wid >> 1;
    const int n0   = blockIdx.x * BN;
    const int m0   = blockIdx.y * BM;
    const int NC   = K / BKc;           // 16

    auto issue = [&](int c) {
        const uint32_t sa = sb + (uint32_t)(c & 1) * STAGE;
        const int k0 = c * BKc;
#pragma unroll
        for (int r = 0; r < 4; r++) {            // A: 1024 16B chunks
            int idx = tid + r * 256;
            int row = idx >> 3, ch = idx & 7;
            CP16(sa + SWZ(row, ch), Ap + (size_t)(m0 + row) * K + k0 + ch * 8);
        }
#pragma unroll
        for (int r = 0; r < 4; r++) {            // B: 1024 16B chunks
            int idx = tid + r * 256;
            int row = idx >> 4, ch = idx & 15;
            CP16(sa + A_BYTES + bswz(row, ch * 8),
                 Bw + (size_t)(k0 + row) * N + n0 + ch * 8);
        }
        CP_COMMIT();
    };

    float acc[4][4][4];
#pragma unroll
    for (int i = 0; i < 4; i++)
#pragma unroll
        for (int j = 0; j < 4; j++)
#pragma unroll
            for (int q = 0; q < 4; q++) acc[i][j][q] = 0.f;

    issue(0);
    for (int c = 0; c < NC; c++) {
        CP_WAITG(0);
        __syncthreads();
        if (c + 1 < NC) issue(c + 1);

        const uint32_t sa  = sb + (uint32_t)(c & 1) * STAGE;
        const uint32_t sbw = sa + A_BYTES;

#pragma unroll
        for (int s = 0; s < 4; s++) {             // 4 k16-steps per chunk
            uint32_t ah[4][4];
            uint32_t bw[4][2];
#pragma unroll
            for (int t = 0; t < 4; t++) {
                int row = wm * 64 + t * 16 + (lane & 15);
                ldsm_x4(ah[t], sa + SWZ(row, 2 * s + (lane >> 4)));
            }
#pragma unroll
            for (int p = 0; p < 2; p++) {
                int row  = s * 16 + (lane & 15);
                int ncol = wn * 32 + p * 16 + ((lane >> 4) << 3);
                uint32_t r[4];
                ldsm_x4_t(r, sbw + bswz(row, ncol));
                bw[2*p][0]   = r[0]; bw[2*p][1]   = r[1];
                bw[2*p+1][0] = r[2]; bw[2*p+1][1] = r[3];
            }
#pragma unroll
            for (int t = 0; t < 4; t++)
#pragma unroll
                for (int nn = 0; nn < 4; nn++)
                    mma_f16(acc[t][nn], ah[t], bw[nn][0], bw[nn][1]);
        }
    }

    const int grow = lane >> 2;
    const int gcol = (lane & 3) * 2;

    if (mode == 0) {
#pragma unroll
        for (int nn = 0; nn < 4; nn++) {
            int col = n0 + wn * 32 + nn * 8 + gcol;
            float2 bv = *(const float2*)&bias[col];
#pragma unroll
            for (int t = 0; t < 4; t++) {
                int row0 = m0 + wm * 64 + t * 16 + grow;
                float2 o0 = {acc[t][nn][0] + bv.x, acc[t][nn][1] + bv.y};
                float2 o1 = {acc[t][nn][2] + bv.x, acc[t][nn][3] + bv.y};
                *(float2*)&C[(size_t)row0 * N + col] = o0;
                *(float2*)&C[(size_t)(row0 + 8) * N + col] = o1;
            }
        }
    } else {
        // scatter to [B][H][S][64] plain fp16; q pre-scaled by QSCALE
        const int colb = n0 + wn * 32;
        const int t3 = colb >> 10;               // 0=q 1=k 2=v (warp-uniform)
        const int hh = (colb & 1023) >> 6;
        const int bidx = m0 >> 11;
        __half* dst = (t3 == 0) ? qq : (t3 == 1) ? kk : vv;
        const float sc = (t3 == 0) ? QSCALE : 1.f;
#pragma unroll
        for (int nn = 0; nn < 4; nn++) {
            int col = colb + nn * 8 + gcol;
            int d = col & 63;
            float2 bv = *(const float2*)&bias[col];
#pragma unroll
            for (int t = 0; t < 4; t++) {
                int row0 = m0 + wm * 64 + t * 16 + grow;
                int s = row0 & 2047;
                size_t base  = ((size_t)(bidx * Hn + hh) * Sn + s) * 64 + d;
                size_t base8 = base + 8 * 64;
                float vx = (acc[t][nn][0] + bv.x) * sc, vy = (acc[t][nn][1] + bv.y) * sc;
                float wx = (acc[t][nn][2] + bv.x) * sc, wy = (acc[t][nn][3] + bv.y) * sc;
                *(uint32_t*)&dst[base]  = pack_f16(vx, vy);
                *(uint32_t*)&dst[base8] = pack_f16(wx, wy);
            }
        }
    }
}

// ---------------------------------------------------------------------------
// Tensor-core flash attention, plain fp16 Q/K/V/P, exp2-domain softmax.
// CTA = 128 q rows of one (b,h); 8 warps x 16 rows; 64-key tiles, 4-stage KV.
// smem: Q 16KB + 4 stages x (K 8KB + V 8KB) = 80KB.
// ---------------------------------------------------------------------------
#define KVSTAGES 4
#define ASMEM (16384 + KVSTAGES * 16384)   // 81920

__global__ __launch_bounds__(256, 2) void attn_mma_kernel(
    const __half* __restrict__ Qp,
    const __half* __restrict__ Kp, const __half* __restrict__ Vp,
    __half* __restrict__ outp)
{
    extern __shared__ char sma[];
    const uint32_t sb = smem_u32(sma);
    const uint32_t sQ = sb;
    const int tid = threadIdx.x, wid = tid >> 5, lane = tid & 31;
    const int qt = (gridDim.x - 1) - blockIdx.x;    // heavy tiles first
    const int h = blockIdx.y, b = blockIdx.z;
    const int q0 = qt * 128;
    const size_t head = ((size_t)(b * Hn + h)) * Sn * 64;

    // Q tile: group 0
    for (int i = tid; i < 1024; i += 256) {
        int row = i >> 3, c = i & 7;
        CP16(sQ + SWZ(row, c), Qp + head + (size_t)(q0 + row) * 64 + c * 8);
    }
    CP_COMMIT();

    auto issue_kv = [&](int kt) {
        uint32_t st = sb + 16384 + (uint32_t)(kt & (KVSTAGES - 1)) * 16384;
        const int k0 = kt * 64;
        for (int i = tid; i < 512; i += 256) {
            int row = i >> 3, c = i & 7;
            uint32_t d = SWZ(row, c);
            size_t g = head + (size_t)(k0 + row) * 64 + c * 8;
            CP16(st + d,        Kp + g);
            CP16(st + 8192 + d, Vp + g);
        }
        CP_COMMIT();
    };

    const int nkt = 2 * qt + 2;
#pragma unroll
    for (int kt = 0; kt < 3; kt++) {
        if (kt < nkt) issue_kv(kt); else CP_COMMIT();
    }
    CP_WAITG(3);          // Q (group 0) complete
    __syncthreads();

    const int qr      = wid * 16 + (lane & 15);
    const int qc_add  = (lane >> 4);
    const int kr_base = ((lane >> 4) << 3) + (lane & 7);
    const int kc_add  = ((lane >> 3) & 1);
    const int vr      = (lane & 15);

    // hoist Q fragments to registers
    uint32_t qhr[4][4];
#pragma unroll
    for (int ks = 0; ks < 4; ks++)
        ldsm_x4(qhr[ks], sQ + SWZ(qr, 2 * ks + qc_add));

    float oacc[8][4];
#pragma unroll
    for (int j = 0; j < 8; j++)
#pragma unroll
        for (int q = 0; q < 4; q++) oacc[j][q] = 0.f;
    float m[2] = {-1e30f, -1e30f}, l[2] = {0.f, 0.f};

    for (int c = 0; c < nkt; c++) {
        CP_WAITG(2);
        __syncthreads();
        if (c + 3 < nkt) issue_kv(c + 3); else CP_COMMIT();

        const uint32_t stK = sb + 16384 + (uint32_t)(c & (KVSTAGES - 1)) * 16384;
        const uint32_t stV = stK + 8192;
        const int k0 = c * 64;

        // ---- S = Q K^T ----
        float sacc[8][4];
#pragma unroll
        for (int j = 0; j < 8; j++)
#pragma unroll
            for (int q = 0; q < 4; q++) sacc[j][q] = 0.f;

#pragma unroll
        for (int ks = 0; ks < 4; ks++) {
#pragma unroll
            for (int kg = 0; kg < 4; kg++) {
                uint32_t kh4[4];
                ldsm_x4(kh4, stK + SWZ(kg * 16 + kr_base, 2 * ks + kc_add));
                mma_f16(sacc[2*kg],   qhr[ks], kh4[0], kh4[1]);
                mma_f16(sacc[2*kg+1], qhr[ks], kh4[2], kh4[3]);
            }
        }

        // ---- causal mask ----
        const int r0g = q0 + wid * 16 + (lane >> 2);
        if (k0 + 63 > q0 + wid * 16) {
#pragma unroll
            for (int j = 0; j < 8; j++) {
                int key = k0 + 8 * j + (lane & 3) * 2;
                if (key     > r0g)     sacc[j][0] = -1e30f;
                if (key + 1 > r0g)     sacc[j][1] = -1e30f;
                if (key     > r0g + 8) sacc[j][2] = -1e30f;
                if (key + 1 > r0g + 8) sacc[j][3] = -1e30f;
            }
        }

        // ---- online softmax (exp2 domain) per row-group ----
#pragma unroll
        for (int rg = 0; rg < 2; rg++) {
            float tm = -1e30f;
#pragma unroll
            for (int j = 0; j < 8; j++)
                tm = fmaxf(tm, fmaxf(sacc[j][2*rg], sacc[j][2*rg+1]));
            tm = fmaxf(tm, __shfl_xor_sync(0xffffffffu, tm, 1));
            tm = fmaxf(tm, __shfl_xor_sync(0xffffffffu, tm, 2));
            float mnew = fmaxf(m[rg], tm);
            float corr = ex2(m[rg] - mnew);
            m[rg] = mnew;
            float rs = 0.f;
#pragma unroll
            for (int j = 0; j < 8; j++) {
                float e0 = ex2(sacc[j][2*rg]   - mnew);
                float e1 = ex2(sacc[j][2*rg+1] - mnew);
                sacc[j][2*rg] = e0; sacc[j][2*rg+1] = e1;
                rs += e0 + e1;
            }
            rs += __shfl_xor_sync(0xffffffffu, rs, 1);
            rs += __shfl_xor_sync(0xffffffffu, rs, 2);
            l[rg] = l[rg] * corr + rs;
#pragma unroll
            for (int j = 0; j < 8; j++) {
                oacc[j][2*rg]   *= corr;
                oacc[j][2*rg+1] *= corr;
            }
        }

        // ---- O += P V ----
#pragma unroll
        for (int t = 0; t < 4; t++) {
            uint32_t phi[4];
            phi[0] = pack_f16(sacc[2*t][0],   sacc[2*t][1]);
            phi[1] = pack_f16(sacc[2*t][2],   sacc[2*t][3]);
            phi[2] = pack_f16(sacc[2*t+1][0], sacc[2*t+1][1]);
            phi[3] = pack_f16(sacc[2*t+1][2], sacc[2*t+1][3]);
            int vrow = t * 16 + vr;
#pragma unroll
            for (int p = 0; p < 4; p++) {
                uint32_t vh4[4];
                ldsm_x4_t(vh4, stV + SWZ(vrow, 2 * p + qc_add));
                mma_f16(oacc[2*p],   phi, vh4[0], vh4[1]);
                mma_f16(oacc[2*p+1], phi, vh4[2], vh4[3]);
            }
        }
    }

    // ---- normalize + plain fp16 store to [row=(b,s)][h*64+d] ----
    const float inv0 = 1.f / l[0], inv1 = 1.f / l[1];
    const int s0 = q0 + wid * 16 + (lane >> 2);
#pragma unroll
    for (int j = 0; j < 8; j++) {
        int dcol = h * 64 + 8 * j + (lane & 3) * 2;
        size_t i0 = (size_t)(b * Sn + s0) * HHD + dcol;
        size_t i1 = i0 + (size_t)8 * HHD;
        *(uint32_t*)&outp[i0] = pack_f16(oacc[j][0] * inv0, oacc[j][1] * inv0);
        *(uint32_t*)&outp[i1] = pack_f16(oacc[j][2] * inv1, oacc[j][3] * inv1);
    }
}

// ---------------------------------------------------------------------------
extern "C" void kernel_launch(void* const* d_in, const int* in_sizes, int n_in,
                              void* d_out, int out_size)
{
    const float* x      = (const float*)d_in[0];
    const float* w_qkv  = (const float*)d_in[1];
    const float* b_qkv  = (const float*)d_in[2];
    const float* w_proj = (const float*)d_in[3];
    const float* b_proj = (const float*)d_in[4];
    float* out = (float*)d_out;

    __half *xh, *wq, *wp, *att, *qq, *kk, *vv;
    cudaGetSymbolAddress((void**)&xh, g_x);
    cudaGetSymbolAddress((void**)&wq, g_wqkv);
    cudaGetSymbolAddress((void**)&wp, g_wproj);
    cudaGetSymbolAddress((void**)&att, g_att);
    cudaGetSymbolAddress((void**)&qq, g_q);
    cudaGetSymbolAddress((void**)&kk, g_k);
    cudaGetSymbolAddress((void**)&vv, g_v);

    cudaFuncSetAttribute(gemm_f16_kernel,
                         cudaFuncAttributeMaxDynamicSharedMemorySize, SMEM_G);
    cudaFuncSetAttribute(attn_mma_kernel,
                         cudaFuncAttributeMaxDynamicSharedMemorySize, ASMEM);

    // fused prep (x + both weights -> plain fp16)
    prep_kernel<<<(NX4 + NW14 + NW24) / 256, 256>>>(x, w_qkv, w_proj, xh, wq, wp);

    // 1) QKV GEMM -> head-major q(QSCALE)/k/v plain fp16
    gemm_f16_kernel<<<dim3(QKVROW / BN, Mrows / BM), 256, SMEM_G>>>(
        xh, wq, b_qkv, nullptr, qq, kk, vv, Mrows, QKVROW, Dn, 1);

    // 2) tensor-core causal flash attention -> att plain fp16
    attn_mma_kernel<<<dim3(Sn / 128, Hn, Bn), 256, ASMEM>>>(qq, kk, vv, att);

    // 3) proj GEMM -> fp32 out + bias
    gemm_f16_kernel<<<dim3(Dn / BN, Mrows / BM), 256, SMEM_G>>>(
        att, wp, b_proj, out, nullptr, nullptr, nullptr, Mrows, Dn, HHD, 0);
}